// round 10
// baseline (speedup 1.0000x reference)
#include <cuda_runtime.h>
#include <cuda_fp16.h>
#include <cstdint>
#include <math.h>

// SpatialGRU: B=256, C=128, L1=L2=32, U=128
// R9 skeleton (63 x {k1,k2}, fp16 m16n8k16, ldmatrix, 2-stage cp.async),
// 1024 threads/block (32 warps, 8x4 warp grid, 16x32 warp tiles).

#define NP  1024
#define BSZ 256
#define NTHR 1024

// ---- device scratch (no allocation allowed) ----
__device__ __half g_Th [NP * BSZ * 128];  // s, fp16 (MMA operand)
__device__ float  g_H  [NP * BSZ * 128];  // h, fp32 (epilogue operand)
__device__ __half g_Hr [NP * BSZ * 128];  // h, fp16 (MMA operand)
__device__ __half g_WpT[896 * 512];       // W^T col-permuted, [n][k]
__device__ __half g_U2T[128 * 512];       // [Umat;w_ij]^T, [n][k]
__device__ float  g_bP [896];             // permuted bias
__device__ __half g_A2 [8192 * 384];      // GEMM2 A (r*h parts)
__device__ float  g_Z  [8192 * 512];      // softmaxed gates [m][u*4+g]

__device__ __forceinline__ void mma16(float* c, const uint32_t* a, uint32_t b0, uint32_t b1) {
    asm volatile("mma.sync.aligned.m16n8k16.row.col.f32.f16.f16.f32 "
        "{%0,%1,%2,%3},{%4,%5,%6,%7},{%8,%9},{%0,%1,%2,%3};"
        : "+f"(c[0]), "+f"(c[1]), "+f"(c[2]), "+f"(c[3])
        : "r"(a[0]), "r"(a[1]), "r"(a[2]), "r"(a[3]), "r"(b0), "r"(b1));
}
__device__ __forceinline__ void cp16(uint32_t dst, const void* src, int sz) {
    asm volatile("cp.async.cg.shared.global [%0], [%1], 16, %2;" :: "r"(dst), "l"(src), "r"(sz));
}
__device__ __forceinline__ void ldsm4(uint32_t* r, uint32_t a) {
    asm volatile("ldmatrix.sync.aligned.m8n8.x4.shared.b16 {%0,%1,%2,%3}, [%4];"
        : "=r"(r[0]), "=r"(r[1]), "=r"(r[2]), "=r"(r[3]) : "r"(a));
}
__device__ __forceinline__ void ldsm2(uint32_t* r, uint32_t a) {
    asm volatile("ldmatrix.sync.aligned.m8n8.x2.shared.b16 {%0,%1}, [%2];"
        : "=r"(r[0]), "=r"(r[1]) : "r"(a));
}

// ---------------------------------------------------------------------------
// setup (2 launches)
__global__ void transpose_kernel(const float* __restrict__ in) {
    __shared__ float tile[32][33];
    int x  = blockIdx.x * 32 + threadIdx.x;   // p
    int y0 = blockIdx.y * 32;                 // bc
#pragma unroll
    for (int r = 0; r < 4; r++) {
        int y = y0 + threadIdx.y + r * 8;
        tile[threadIdx.y + r * 8][threadIdx.x] = in[(size_t)y * 1024 + x];
    }
    __syncthreads();
    int xo  = blockIdx.y * 32 + threadIdx.x;
    int yo0 = blockIdx.x * 32;
#pragma unroll
    for (int r = 0; r < 4; r++) {
        int yo = yo0 + threadIdx.y + r * 8;
        g_Th[(size_t)yo * 32768 + xo] = __float2half_rn(tile[threadIdx.x][threadIdx.y + r * 8]);
    }
}

#define NWT (896 * 512)
#define NUT (128 * 512)
__global__ void prep_all_kernel(const float* __restrict__ W, const float* __restrict__ Umat,
                                const float* __restrict__ w_ij, const float* __restrict__ bias) {
    int idx = blockIdx.x * 256 + threadIdx.x;
    if (idx < NWT) {
        int n = idx >> 9, k = idx & 511;
        int corig = (n < 384) ? n : 384 + ((n - 384) & 3) * 128 + ((n - 384) >> 2);
        g_WpT[idx] = __float2half_rn(W[(size_t)k * 896 + corig]);
    } else if (idx < NWT + NUT) {
        int t = idx - NWT;
        int n = t >> 9, k = t & 511;
        g_U2T[t] = __float2half_rn((k < 384) ? Umat[k * 128 + n] : w_ij[(k - 384) * 128 + n]);
    } else if (idx < NWT + NUT + 896) {
        int c = idx - NWT - NUT;
        if (c < 384) g_bP[c] = bias[c];
        else {
            int cc = c - 384, u = cc >> 2, g = cc & 3;
            g_bP[c] = bias[384 + g * 128 + u];
        }
    }
}

// ---------------------------------------------------------------------------
#define STRH  72                       // smem row stride in halves (144B)
#define AHALF (128 * STRH)             // halves per A (or B) tile
#define STGH  (2 * AHALF)              // halves per stage
#define SMEM_BYTES (2 * STGH * 2)      // 73728

// inner MMA loop over one staged buffer (32 warps, 16x32 warp tiles)
#define MMA_TILE(aB_)  do {                                                     \
        const uint32_t bBv_ = (aB_) + AHALF * 2;                                \
        _Pragma("unroll")                                                       \
        for (int k16 = 0; k16 < 4; k16++) {                                     \
            const uint32_t kb2 = k16 * 32;                                      \
            uint32_t af[4];                                                     \
            ldsm4(af, (aB_) + aOff0 + kb2);                                     \
            _Pragma("unroll")                                                   \
            for (int nt = 0; nt < 4; nt++) {                                    \
                uint32_t bf[2];                                                 \
                ldsm2(bf, bBv_ + bOff + nt * (8 * STRH * 2) + kb2);             \
                mma16(acc[nt], af, bf[0], bf[1]);                               \
            }                                                                   \
        }                                                                       \
    } while (0)

// K1: rz = q @ Wp ; gate epilogue. grid = (7 ntiles, nc*2 mtiles), 1024 thr.
__global__ __launch_bounds__(NTHR) void k1_kernel(int d) {
    extern __shared__ __half sm[];
    const uint32_t smA0 = (uint32_t)__cvta_generic_to_shared(sm);

    const int tid = threadIdx.x, lane = tid & 31, warp = tid >> 5;
    const int wm = warp >> 2, wn = warp & 3, qj = lane & 3, ql = lane >> 2;
    const int i0 = (d > 31) ? d - 31 : 0;
    const int Mbase = blockIdx.y * 128;
    const int cell = Mbase >> 8, b0 = Mbase & 255;
    const int i = i0 + cell, j = d - i, p = i * 32 + j;
    const int nc0 = blockIdx.x * 128;

    // ldmatrix lane address offsets (bytes)
    const int l15 = lane & 15, lhi = lane >> 4;
    const uint32_t aOff0 = ((wm * 16 + l15) * STRH + lhi * 8) * 2;
    const uint32_t bOff  = ((wn * 32 + (lane & 7)) * STRH + ((lane >> 3) & 1) * 8) * 2;

    const __half* src[4]; int vld[4];
    vld[0] = (i > 0) ? 16 : 0;
    vld[1] = (j > 0) ? 16 : 0;
    vld[2] = (i > 0 && j > 0) ? 16 : 0;
    vld[3] = 16;
    src[0] = vld[0] ? g_Hr + ((size_t)(p - 32) * BSZ + b0) * 128 : g_Th;
    src[1] = vld[1] ? g_Hr + ((size_t)(p - 1 ) * BSZ + b0) * 128 : g_Th;
    src[2] = vld[2] ? g_Hr + ((size_t)(p - 33) * BSZ + b0) * 128 : g_Th;
    src[3] = g_Th + ((size_t)p * BSZ + b0) * 128;

    float acc[4][4] = {};

#define STAGE1(t, buf) do {                                                     \
        int seg_ = (t) >> 1;                                                    \
        const __half* sp_ = src[seg_]; int v_ = vld[seg_];                      \
        int kof_ = ((t) & 1) * 64;                                              \
        uint32_t aB_ = smA0 + (buf) * (STGH * 2);                               \
        uint32_t bB_ = aB_ + AHALF * 2;                                         \
        {                                                                       \
            int m_ = tid >> 3, c_ = tid & 7;                                    \
            cp16(aB_ + (m_ * STRH + c_ * 8) * 2,                                \
                 sp_ + (size_t)m_ * 128 + kof_ + c_ * 8, v_);                   \
        }                                                                       \
        const __half* wp_ = g_WpT + (size_t)nc0 * 512 + (t) * 64;               \
        {                                                                       \
            int n_ = tid >> 3, c_ = tid & 7;                                    \
            cp16(bB_ + (n_ * STRH + c_ * 8) * 2,                                \
                 wp_ + (size_t)n_ * 512 + c_ * 8, 16);                          \
        }                                                                       \
        asm volatile("cp.async.commit_group;");                                 \
    } while (0)

    STAGE1(0, 0);
#pragma unroll 1
    for (int t = 0; t < 8; t++) {
        int buf = t & 1;
        if (t < 7) { STAGE1(t + 1, buf ^ 1); asm volatile("cp.async.wait_group 1;"); }
        else       { asm volatile("cp.async.wait_group 0;"); }
        __syncthreads();
        const uint32_t aB = smA0 + buf * (STGH * 2);
        MMA_TILE(aB);
        __syncthreads();
    }

    // ---- epilogue ----
    if (nc0 < 384) {
        const float* hsrc[3];
        hsrc[0] = (j > 0)          ? g_H + ((size_t)(p - 1 ) * BSZ + b0) * 128 : nullptr;
        hsrc[1] = (i > 0)          ? g_H + ((size_t)(p - 32) * BSZ + b0) * 128 : nullptr;
        hsrc[2] = (i > 0 && j > 0) ? g_H + ((size_t)(p - 33) * BSZ + b0) * 128 : nullptr;
#pragma unroll
        for (int half = 0; half < 2; half++) {
            int lr = wm * 16 + ql + half * 8;
            int Mr = Mbase + lr;
#pragma unroll
            for (int nt = 0; nt < 4; nt++) {
                int c = nc0 + wn * 32 + nt * 8 + 2 * qj;
                float v0 = acc[nt][half * 2 + 0] + g_bP[c];
                float v1 = acc[nt][half * 2 + 1] + g_bP[c + 1];
                v0 = fminf(fmaxf(0.2f * v0 + 0.5f, 0.f), 1.f);
                v1 = fminf(fmaxf(0.2f * v1 + 0.5f, 0.f), 1.f);
                int seg = c >> 7, u = c & 127;
                const float* hp = hsrc[seg];
                float h0 = hp ? hp[lr * 128 + u]     : 0.f;
                float h1 = hp ? hp[lr * 128 + u + 1] : 0.f;
                *(__half2*)&g_A2[(size_t)Mr * 384 + c] =
                    __floats2half2_rn(v0 * h0, v1 * h1);
            }
        }
    } else {
#pragma unroll
        for (int half = 0; half < 2; half++) {
            int lr = wm * 16 + ql + half * 8;
            int Mr = Mbase + lr;
#pragma unroll
            for (int nt = 0; nt < 4; nt++) {
                int c = nc0 + wn * 32 + nt * 8 + 2 * qj;
                float z0 = acc[nt][half * 2 + 0] + g_bP[c];
                float z1 = acc[nt][half * 2 + 1] + g_bP[c + 1];
                float q0 = __shfl_xor_sync(0xffffffffu, z0, 1);
                float q1 = __shfl_xor_sync(0xffffffffu, z1, 1);
                float mx = fmaxf(fmaxf(z0, z1), fmaxf(q0, q1));
                float e0 = __expf(z0 - mx), e1 = __expf(z1 - mx);
                float s2 = e0 + e1;
                float st = s2 + __shfl_xor_sync(0xffffffffu, s2, 1);
                float inv = 1.f / st;
                int cc = c - 384, u = cc >> 2, g = cc & 3;
                *(float2*)&g_Z[(size_t)Mr * 512 + u * 4 + g] =
                    make_float2(e0 * inv, e1 * inv);
            }
        }
    }
}

// K2: hstar = tanh(A2 @ U2 + b_ij); h = zl*hl + zt*ht + zd*hd + zi*hstar
__global__ __launch_bounds__(NTHR) void k2_kernel(int d, const float* __restrict__ bias,
                                                  float* __restrict__ out) {
    extern __shared__ __half sm[];
    const uint32_t smA0 = (uint32_t)__cvta_generic_to_shared(sm);

    const int tid = threadIdx.x, lane = tid & 31, warp = tid >> 5;
    const int wm = warp >> 2, wn = warp & 3, qj = lane & 3, ql = lane >> 2;
    const int i0 = (d > 31) ? d - 31 : 0;
    const int Mbase = blockIdx.x * 128;
    const int cell = Mbase >> 8, b0 = Mbase & 255;
    const int i = i0 + cell, j = d - i, p = i * 32 + j;

    const int l15 = lane & 15, lhi = lane >> 4;
    const uint32_t aOff0 = ((wm * 16 + l15) * STRH + lhi * 8) * 2;
    const uint32_t bOff  = ((wn * 32 + (lane & 7)) * STRH + ((lane >> 3) & 1) * 8) * 2;

    const __half* Tsrc = g_Th + ((size_t)p * BSZ + b0) * 128;
    float acc[4][4] = {};

#define STAGE2(t, buf) do {                                                     \
        uint32_t aB_ = smA0 + (buf) * (STGH * 2);                               \
        uint32_t bB_ = aB_ + AHALF * 2;                                         \
        {                                                                       \
            int m_ = tid >> 3, c_ = tid & 7;                                    \
            const __half* sp_;                                                  \
            if ((t) < 6) sp_ = g_A2 + (size_t)(Mbase + m_) * 384 + (t) * 64 + c_ * 8;   \
            else         sp_ = Tsrc + (size_t)m_ * 128 + ((t) - 6) * 64 + c_ * 8;       \
            cp16(aB_ + (m_ * STRH + c_ * 8) * 2, sp_, 16);                      \
        }                                                                       \
        const __half* up_ = g_U2T + (size_t)(t) * 64;                           \
        {                                                                       \
            int n_ = tid >> 3, c_ = tid & 7;                                    \
            cp16(bB_ + (n_ * STRH + c_ * 8) * 2,                                \
                 up_ + (size_t)n_ * 512 + c_ * 8, 16);                          \
        }                                                                       \
        asm volatile("cp.async.commit_group;");                                 \
    } while (0)

    STAGE2(0, 0);
#pragma unroll 1
    for (int t = 0; t < 8; t++) {
        int buf = t & 1;
        if (t < 7) { STAGE2(t + 1, buf ^ 1); asm volatile("cp.async.wait_group 1;"); }
        else       { asm volatile("cp.async.wait_group 0;"); }
        __syncthreads();
        const uint32_t aB = smA0 + buf * (STGH * 2);
        MMA_TILE(aB);
        __syncthreads();
    }

    const float* hL = (j > 0)          ? g_H + ((size_t)(p - 1 ) * BSZ + b0) * 128 : nullptr;
    const float* hT = (i > 0)          ? g_H + ((size_t)(p - 32) * BSZ + b0) * 128 : nullptr;
    const float* hD = (i > 0 && j > 0) ? g_H + ((size_t)(p - 33) * BSZ + b0) * 128 : nullptr;
    float*  Hd  = g_H  + ((size_t)p * BSZ + b0) * 128;
    __half* Hrd = g_Hr + ((size_t)p * BSZ + b0) * 128;

#pragma unroll
    for (int half = 0; half < 2; half++) {
        int lr = wm * 16 + ql + half * 8;
        int Mr = Mbase + lr;
#pragma unroll
        for (int nt = 0; nt < 4; nt++) {
            int u = wn * 32 + nt * 8 + 2 * qj;
            float a0 = acc[nt][half * 2 + 0] + bias[896 + u];
            float a1 = acc[nt][half * 2 + 1] + bias[896 + u + 1];
            float hs0 = tanhf(a0), hs1 = tanhf(a1);
            float4 z0 = *(const float4*)&g_Z[(size_t)Mr * 512 + u * 4];
            float4 z1 = *(const float4*)&g_Z[(size_t)Mr * 512 + (u + 1) * 4];
            float l0 = hL ? hL[lr * 128 + u] : 0.f, l1 = hL ? hL[lr * 128 + u + 1] : 0.f;
            float t0 = hT ? hT[lr * 128 + u] : 0.f, t1 = hT ? hT[lr * 128 + u + 1] : 0.f;
            float d0 = hD ? hD[lr * 128 + u] : 0.f, d1 = hD ? hD[lr * 128 + u + 1] : 0.f;
            float h0 = z0.y * l0 + z0.z * t0 + z0.w * d0 + z0.x * hs0;
            float h1 = z1.y * l1 + z1.z * t1 + z1.w * d1 + z1.x * hs1;
            *(float2*)&Hd[lr * 128 + u]   = make_float2(h0, h1);
            *(__half2*)&Hrd[lr * 128 + u] = __floats2half2_rn(h0, h1);
            if (p == 1023)
                *(float2*)&out[(size_t)(b0 + lr) * 128 + u] = make_float2(h0, h1);
        }
    }
}

// ---------------------------------------------------------------------------
extern "C" void kernel_launch(void* const* d_in, const int* in_sizes, int n_in,
                              void* d_out, int out_size) {
    const float* inputs = (const float*)d_in[0];
    const float* W      = (const float*)d_in[1];
    const float* Umat   = (const float*)d_in[2];
    const float* bias   = (const float*)d_in[3];
    const float* w_ij   = (const float*)d_in[4];
    float* out = (float*)d_out;

    cudaFuncSetAttribute(k1_kernel, cudaFuncAttributeMaxDynamicSharedMemorySize, SMEM_BYTES);
    cudaFuncSetAttribute(k2_kernel, cudaFuncAttributeMaxDynamicSharedMemorySize, SMEM_BYTES);

    transpose_kernel<<<dim3(32, 1024), dim3(32, 8)>>>(inputs);
    prep_all_kernel<<<(NWT + NUT + 896 + 255) / 256, 256>>>(W, Umat, w_ij, bias);

    for (int d = 0; d <= 62; d++) {
        int i0 = (d > 31) ? d - 31 : 0;
        int i1 = (d < 31) ? d : 31;
        int nc = i1 - i0 + 1;
        k1_kernel<<<dim3(7, nc * 2), NTHR, SMEM_BYTES>>>(d);
        k2_kernel<<<dim3(nc * 2), NTHR, SMEM_BYTES>>>(d, bias, out);
    }
    (void)in_sizes; (void)n_in; (void)out_size;
}

// round 11
// speedup vs baseline: 1.1278x; 1.1278x over previous
#include <cuda_runtime.h>
#include <cuda_fp16.h>
#include <cstdint>
#include <math.h>

// SpatialGRU: B=256, C=128, L1=L2=32, U=128
// Hybrid: k1 = R9 (512 thr, Ktile 64, 3 blocks/SM on wide diagonals);
//         k2 = 1024 thr, Ktile 128 (4 k-iters, half the barriers).
// fp16 m16n8k16, ldmatrix, 2-stage cp.async.

#define NP  1024
#define BSZ 256
#define NT1 512
#define NT2 1024

// ---- device scratch (no allocation allowed) ----
__device__ __half g_Th [NP * BSZ * 128];  // s, fp16 (MMA operand)
__device__ float  g_H  [NP * BSZ * 128];  // h, fp32 (epilogue operand)
__device__ __half g_Hr [NP * BSZ * 128];  // h, fp16 (MMA operand)
__device__ __half g_WpT[896 * 512];       // W^T col-permuted, [n][k]
__device__ __half g_U2T[128 * 512];       // [Umat;w_ij]^T, [n][k]
__device__ float  g_bP [896];             // permuted bias
__device__ __half g_A2 [8192 * 384];      // GEMM2 A (r*h parts)
__device__ float  g_Z  [8192 * 512];      // softmaxed gates [m][u*4+g]

__device__ __forceinline__ void mma16(float* c, const uint32_t* a, uint32_t b0, uint32_t b1) {
    asm volatile("mma.sync.aligned.m16n8k16.row.col.f32.f16.f16.f32 "
        "{%0,%1,%2,%3},{%4,%5,%6,%7},{%8,%9},{%0,%1,%2,%3};"
        : "+f"(c[0]), "+f"(c[1]), "+f"(c[2]), "+f"(c[3])
        : "r"(a[0]), "r"(a[1]), "r"(a[2]), "r"(a[3]), "r"(b0), "r"(b1));
}
__device__ __forceinline__ void cp16(uint32_t dst, const void* src, int sz) {
    asm volatile("cp.async.cg.shared.global [%0], [%1], 16, %2;" :: "r"(dst), "l"(src), "r"(sz));
}
__device__ __forceinline__ void ldsm4(uint32_t* r, uint32_t a) {
    asm volatile("ldmatrix.sync.aligned.m8n8.x4.shared.b16 {%0,%1,%2,%3}, [%4];"
        : "=r"(r[0]), "=r"(r[1]), "=r"(r[2]), "=r"(r[3]) : "r"(a));
}
__device__ __forceinline__ void ldsm2(uint32_t* r, uint32_t a) {
    asm volatile("ldmatrix.sync.aligned.m8n8.x2.shared.b16 {%0,%1}, [%2];"
        : "=r"(r[0]), "=r"(r[1]) : "r"(a));
}

// ---------------------------------------------------------------------------
// setup (2 launches)
__global__ void transpose_kernel(const float* __restrict__ in) {
    __shared__ float tile[32][33];
    int x  = blockIdx.x * 32 + threadIdx.x;   // p
    int y0 = blockIdx.y * 32;                 // bc
#pragma unroll
    for (int r = 0; r < 4; r++) {
        int y = y0 + threadIdx.y + r * 8;
        tile[threadIdx.y + r * 8][threadIdx.x] = in[(size_t)y * 1024 + x];
    }
    __syncthreads();
    int xo  = blockIdx.y * 32 + threadIdx.x;
    int yo0 = blockIdx.x * 32;
#pragma unroll
    for (int r = 0; r < 4; r++) {
        int yo = yo0 + threadIdx.y + r * 8;
        g_Th[(size_t)yo * 32768 + xo] = __float2half_rn(tile[threadIdx.x][threadIdx.y + r * 8]);
    }
}

#define NWT (896 * 512)
#define NUT (128 * 512)
__global__ void prep_all_kernel(const float* __restrict__ W, const float* __restrict__ Umat,
                                const float* __restrict__ w_ij, const float* __restrict__ bias) {
    int idx = blockIdx.x * 256 + threadIdx.x;
    if (idx < NWT) {
        int n = idx >> 9, k = idx & 511;
        int corig = (n < 384) ? n : 384 + ((n - 384) & 3) * 128 + ((n - 384) >> 2);
        g_WpT[idx] = __float2half_rn(W[(size_t)k * 896 + corig]);
    } else if (idx < NWT + NUT) {
        int t = idx - NWT;
        int n = t >> 9, k = t & 511;
        g_U2T[t] = __float2half_rn((k < 384) ? Umat[k * 128 + n] : w_ij[(k - 384) * 128 + n]);
    } else if (idx < NWT + NUT + 896) {
        int c = idx - NWT - NUT;
        if (c < 384) g_bP[c] = bias[c];
        else {
            int cc = c - 384, u = cc >> 2, g = cc & 3;
            g_bP[c] = bias[384 + g * 128 + u];
        }
    }
}

// ---------------------------------------------------------------------------
// k1 (R9 config): 512 threads, Ktile 64, STRH 72
#define STRH  72
#define AHALF (128 * STRH)
#define STGH  (2 * AHALF)
#define SMEM1 (2 * STGH * 2)            // 73728

#define MMA_TILE1(aB_)  do {                                                     \
        const uint32_t bBv_ = (aB_) + AHALF * 2;                                 \
        _Pragma("unroll")                                                        \
        for (int k16 = 0; k16 < 4; k16++) {                                      \
            const uint32_t kb2 = k16 * 32;                                       \
            uint32_t af0[4], af1[4];                                             \
            ldsm4(af0, (aB_) + aOff0 + kb2);                                     \
            ldsm4(af1, (aB_) + aOff1 + kb2);                                     \
            _Pragma("unroll")                                                    \
            for (int nt = 0; nt < 4; nt++) {                                     \
                uint32_t bf[2];                                                  \
                ldsm2(bf, bBv_ + bOff + nt * (8 * STRH * 2) + kb2);              \
                mma16(acc[0][nt], af0, bf[0], bf[1]);                            \
                mma16(acc[1][nt], af1, bf[0], bf[1]);                            \
            }                                                                    \
        }                                                                        \
    } while (0)

__global__ __launch_bounds__(NT1) void k1_kernel(int d) {
    extern __shared__ __half sm[];
    const uint32_t smA0 = (uint32_t)__cvta_generic_to_shared(sm);

    const int tid = threadIdx.x, lane = tid & 31, warp = tid >> 5;
    const int wm = warp >> 2, wn = warp & 3, qj = lane & 3, ql = lane >> 2;
    const int i0 = (d > 31) ? d - 31 : 0;
    const int Mbase = blockIdx.y * 128;
    const int cell = Mbase >> 8, b0 = Mbase & 255;
    const int i = i0 + cell, j = d - i, p = i * 32 + j;
    const int nc0 = blockIdx.x * 128;

    const int l15 = lane & 15, lhi = lane >> 4;
    const uint32_t aOff0 = ((wm * 32 + l15) * STRH + lhi * 8) * 2;
    const uint32_t aOff1 = aOff0 + 16 * STRH * 2;
    const uint32_t bOff  = ((wn * 32 + (lane & 7)) * STRH + ((lane >> 3) & 1) * 8) * 2;

    const __half* src[4]; int vld[4];
    vld[0] = (i > 0) ? 16 : 0;
    vld[1] = (j > 0) ? 16 : 0;
    vld[2] = (i > 0 && j > 0) ? 16 : 0;
    vld[3] = 16;
    src[0] = vld[0] ? g_Hr + ((size_t)(p - 32) * BSZ + b0) * 128 : g_Th;
    src[1] = vld[1] ? g_Hr + ((size_t)(p - 1 ) * BSZ + b0) * 128 : g_Th;
    src[2] = vld[2] ? g_Hr + ((size_t)(p - 33) * BSZ + b0) * 128 : g_Th;
    src[3] = g_Th + ((size_t)p * BSZ + b0) * 128;

    float acc[2][4][4] = {};

#define STAGE1(t, buf) do {                                                     \
        int seg_ = (t) >> 1;                                                    \
        const __half* sp_ = src[seg_]; int v_ = vld[seg_];                      \
        int kof_ = ((t) & 1) * 64;                                              \
        uint32_t aB_ = smA0 + (buf) * (STGH * 2);                               \
        uint32_t bB_ = aB_ + AHALF * 2;                                         \
        _Pragma("unroll")                                                       \
        for (int r_ = 0; r_ < 2; r_++) {                                        \
            int ix_ = tid + r_ * NT1;                                           \
            int m_ = ix_ >> 3, c_ = ix_ & 7;                                    \
            cp16(aB_ + (m_ * STRH + c_ * 8) * 2,                                \
                 sp_ + (size_t)m_ * 128 + kof_ + c_ * 8, v_);                   \
        }                                                                       \
        const __half* wp_ = g_WpT + (size_t)nc0 * 512 + (t) * 64;               \
        _Pragma("unroll")                                                       \
        for (int r_ = 0; r_ < 2; r_++) {                                        \
            int ix_ = tid + r_ * NT1;                                           \
            int n_ = ix_ >> 3, c_ = ix_ & 7;                                    \
            cp16(bB_ + (n_ * STRH + c_ * 8) * 2,                                \
                 wp_ + (size_t)n_ * 512 + c_ * 8, 16);                          \
        }                                                                       \
        asm volatile("cp.async.commit_group;");                                 \
    } while (0)

    STAGE1(0, 0);
#pragma unroll 1
    for (int t = 0; t < 8; t++) {
        int buf = t & 1;
        if (t < 7) { STAGE1(t + 1, buf ^ 1); asm volatile("cp.async.wait_group 1;"); }
        else       { asm volatile("cp.async.wait_group 0;"); }
        __syncthreads();
        const uint32_t aB = smA0 + buf * (STGH * 2);
        MMA_TILE1(aB);
        __syncthreads();
    }

    // ---- epilogue ----
    if (nc0 < 384) {
        const float* hsrc[3];
        hsrc[0] = (j > 0)          ? g_H + ((size_t)(p - 1 ) * BSZ + b0) * 128 : nullptr;
        hsrc[1] = (i > 0)          ? g_H + ((size_t)(p - 32) * BSZ + b0) * 128 : nullptr;
        hsrc[2] = (i > 0 && j > 0) ? g_H + ((size_t)(p - 33) * BSZ + b0) * 128 : nullptr;
#pragma unroll
        for (int mt = 0; mt < 2; mt++) {
#pragma unroll
            for (int half = 0; half < 2; half++) {
                int lr = wm * 32 + mt * 16 + ql + half * 8;
                int Mr = Mbase + lr;
#pragma unroll
                for (int nt = 0; nt < 4; nt++) {
                    int c = nc0 + wn * 32 + nt * 8 + 2 * qj;
                    float v0 = acc[mt][nt][half * 2 + 0] + g_bP[c];
                    float v1 = acc[mt][nt][half * 2 + 1] + g_bP[c + 1];
                    v0 = fminf(fmaxf(0.2f * v0 + 0.5f, 0.f), 1.f);
                    v1 = fminf(fmaxf(0.2f * v1 + 0.5f, 0.f), 1.f);
                    int seg = c >> 7, u = c & 127;
                    const float* hp = hsrc[seg];
                    float h0 = hp ? hp[lr * 128 + u]     : 0.f;
                    float h1 = hp ? hp[lr * 128 + u + 1] : 0.f;
                    *(__half2*)&g_A2[(size_t)Mr * 384 + c] =
                        __floats2half2_rn(v0 * h0, v1 * h1);
                }
            }
        }
    } else {
#pragma unroll
        for (int mt = 0; mt < 2; mt++) {
#pragma unroll
            for (int half = 0; half < 2; half++) {
                int lr = wm * 32 + mt * 16 + ql + half * 8;
                int Mr = Mbase + lr;
#pragma unroll
                for (int nt = 0; nt < 4; nt++) {
                    int c = nc0 + wn * 32 + nt * 8 + 2 * qj;
                    float z0 = acc[mt][nt][half * 2 + 0] + g_bP[c];
                    float z1 = acc[mt][nt][half * 2 + 1] + g_bP[c + 1];
                    float q0 = __shfl_xor_sync(0xffffffffu, z0, 1);
                    float q1 = __shfl_xor_sync(0xffffffffu, z1, 1);
                    float mx = fmaxf(fmaxf(z0, z1), fmaxf(q0, q1));
                    float e0 = __expf(z0 - mx), e1 = __expf(z1 - mx);
                    float s2 = e0 + e1;
                    float st = s2 + __shfl_xor_sync(0xffffffffu, s2, 1);
                    float inv = 1.f / st;
                    int cc = c - 384, u = cc >> 2, g = cc & 3;
                    *(float2*)&g_Z[(size_t)Mr * 512 + u * 4 + g] =
                        make_float2(e0 * inv, e1 * inv);
                }
            }
        }
    }
}

// ---------------------------------------------------------------------------
// k2: 1024 threads, Ktile 128 (4 k-iters), STRH2 136
#define STRH2  136                      // 272B rows: ldmatrix banks 17r mod 32, distinct
#define AHALF2 (128 * STRH2)
#define STGH2  (2 * AHALF2)
#define SMEM2  (2 * STGH2 * 2)          // 139264

#define MMA_TILE2(aB_)  do {                                                     \
        const uint32_t bBv_ = (aB_) + AHALF2 * 2;                                \
        _Pragma("unroll")                                                        \
        for (int k16 = 0; k16 < 8; k16++) {                                      \
            const uint32_t kb2 = k16 * 32;                                       \
            uint32_t af[4];                                                      \
            ldsm4(af, (aB_) + aOff0 + kb2);                                      \
            _Pragma("unroll")                                                    \
            for (int nt = 0; nt < 4; nt++) {                                     \
                uint32_t bf[2];                                                  \
                ldsm2(bf, bBv_ + bOff + nt * (8 * STRH2 * 2) + kb2);             \
                mma16(acc[nt], af, bf[0], bf[1]);                                \
            }                                                                    \
        }                                                                        \
    } while (0)

__global__ __launch_bounds__(NT2) void k2_kernel(int d, const float* __restrict__ bias,
                                                 float* __restrict__ out) {
    extern __shared__ __half sm[];
    const uint32_t smA0 = (uint32_t)__cvta_generic_to_shared(sm);

    const int tid = threadIdx.x, lane = tid & 31, warp = tid >> 5;
    const int wm = warp >> 2, wn = warp & 3, qj = lane & 3, ql = lane >> 2;
    const int i0 = (d > 31) ? d - 31 : 0;
    const int Mbase = blockIdx.x * 128;
    const int cell = Mbase >> 8, b0 = Mbase & 255;
    const int i = i0 + cell, j = d - i, p = i * 32 + j;

    const int l15 = lane & 15, lhi = lane >> 4;
    const uint32_t aOff0 = ((wm * 16 + l15) * STRH2 + lhi * 8) * 2;
    const uint32_t bOff  = ((wn * 32 + (lane & 7)) * STRH2 + ((lane >> 3) & 1) * 8) * 2;

    const __half* Tsrc = g_Th + ((size_t)p * BSZ + b0) * 128;
    float acc[4][4] = {};

#define STAGE2(t, buf) do {                                                     \
        uint32_t aB_ = smA0 + (buf) * (STGH2 * 2);                              \
        uint32_t bB_ = aB_ + AHALF2 * 2;                                        \
        _Pragma("unroll")                                                       \
        for (int r_ = 0; r_ < 2; r_++) {                                        \
            int ix_ = tid + r_ * NT2;                                           \
            int m_ = ix_ >> 4, c_ = ix_ & 15;                                   \
            const __half* sp_;                                                  \
            if ((t) < 3) sp_ = g_A2 + (size_t)(Mbase + m_) * 384 + (t) * 128 + c_ * 8;  \
            else         sp_ = Tsrc + (size_t)m_ * 128 + c_ * 8;                        \
            cp16(aB_ + (m_ * STRH2 + c_ * 8) * 2, sp_, 16);                     \
        }                                                                       \
        const __half* up_ = g_U2T + (size_t)(t) * 128;                          \
        _Pragma("unroll")                                                       \
        for (int r_ = 0; r_ < 2; r_++) {                                        \
            int ix_ = tid + r_ * NT2;                                           \
            int n_ = ix_ >> 4, c_ = ix_ & 15;                                   \
            cp16(bB_ + (n_ * STRH2 + c_ * 8) * 2,                               \
                 up_ + (size_t)n_ * 512 + c_ * 8, 16);                          \
        }                                                                       \
        asm volatile("cp.async.commit_group;");                                 \
    } while (0)

    STAGE2(0, 0);
#pragma unroll 1
    for (int t = 0; t < 4; t++) {
        int buf = t & 1;
        if (t < 3) { STAGE2(t + 1, buf ^ 1); asm volatile("cp.async.wait_group 1;"); }
        else       { asm volatile("cp.async.wait_group 0;"); }
        __syncthreads();
        const uint32_t aB = smA0 + buf * (STGH2 * 2);
        MMA_TILE2(aB);
        __syncthreads();
    }

    const float* hL = (j > 0)          ? g_H + ((size_t)(p - 1 ) * BSZ + b0) * 128 : nullptr;
    const float* hT = (i > 0)          ? g_H + ((size_t)(p - 32) * BSZ + b0) * 128 : nullptr;
    const float* hD = (i > 0 && j > 0) ? g_H + ((size_t)(p - 33) * BSZ + b0) * 128 : nullptr;
    float*  Hd  = g_H  + ((size_t)p * BSZ + b0) * 128;
    __half* Hrd = g_Hr + ((size_t)p * BSZ + b0) * 128;

#pragma unroll
    for (int half = 0; half < 2; half++) {
        int lr = wm * 16 + ql + half * 8;
        int Mr = Mbase + lr;
#pragma unroll
        for (int nt = 0; nt < 4; nt++) {
            int u = wn * 32 + nt * 8 + 2 * qj;
            float a0 = acc[nt][half * 2 + 0] + bias[896 + u];
            float a1 = acc[nt][half * 2 + 1] + bias[896 + u + 1];
            float hs0 = tanhf(a0), hs1 = tanhf(a1);
            float4 z0 = *(const float4*)&g_Z[(size_t)Mr * 512 + u * 4];
            float4 z1 = *(const float4*)&g_Z[(size_t)Mr * 512 + (u + 1) * 4];
            float l0 = hL ? hL[lr * 128 + u] : 0.f, l1 = hL ? hL[lr * 128 + u + 1] : 0.f;
            float t0 = hT ? hT[lr * 128 + u] : 0.f, t1 = hT ? hT[lr * 128 + u + 1] : 0.f;
            float d0 = hD ? hD[lr * 128 + u] : 0.f, d1 = hD ? hD[lr * 128 + u + 1] : 0.f;
            float h0 = z0.y * l0 + z0.z * t0 + z0.w * d0 + z0.x * hs0;
            float h1 = z1.y * l1 + z1.z * t1 + z1.w * d1 + z1.x * hs1;
            *(float2*)&Hd[lr * 128 + u]   = make_float2(h0, h1);
            *(__half2*)&Hrd[lr * 128 + u] = __floats2half2_rn(h0, h1);
            if (p == 1023)
                *(float2*)&out[(size_t)(b0 + lr) * 128 + u] = make_float2(h0, h1);
        }
    }
}

// ---------------------------------------------------------------------------
extern "C" void kernel_launch(void* const* d_in, const int* in_sizes, int n_in,
                              void* d_out, int out_size) {
    const float* inputs = (const float*)d_in[0];
    const float* W      = (const float*)d_in[1];
    const float* Umat   = (const float*)d_in[2];
    const float* bias   = (const float*)d_in[3];
    const float* w_ij   = (const float*)d_in[4];
    float* out = (float*)d_out;

    cudaFuncSetAttribute(k1_kernel, cudaFuncAttributeMaxDynamicSharedMemorySize, SMEM1);
    cudaFuncSetAttribute(k2_kernel, cudaFuncAttributeMaxDynamicSharedMemorySize, SMEM2);

    transpose_kernel<<<dim3(32, 1024), dim3(32, 8)>>>(inputs);
    prep_all_kernel<<<(NWT + NUT + 896 + 255) / 256, 256>>>(W, Umat, w_ij, bias);

    for (int d = 0; d <= 62; d++) {
        int i0 = (d > 31) ? d - 31 : 0;
        int i1 = (d < 31) ? d : 31;
        int nc = i1 - i0 + 1;
        k1_kernel<<<dim3(7, nc * 2), NT1, SMEM1>>>(d);
        k2_kernel<<<dim3(nc * 2), NT2, SMEM2>>>(d, bias, out);
    }
    (void)in_sizes; (void)n_in; (void)out_size;
}

// round 12
// speedup vs baseline: 1.2322x; 1.0926x over previous
#include <cuda_runtime.h>
#include <cuda_fp16.h>
#include <cstdint>
#include <math.h>

// SpatialGRU: B=256, C=128, L1=L2=32, U=128
// R9 kernels (512 thr, fp16 m16n8k16, ldmatrix, 2-stage cp.async) + PDL:
// first 2 stages read only recurrence-independent data (K-order permuted),
// then griddepcontrol.wait; trigger after MMA loop. 63 x {k1,k2} launches.

#define NP  1024
#define BSZ 256
#define NTHR 512

// ---- device scratch (no allocation allowed) ----
__device__ __half g_Th [NP * BSZ * 128];  // s, fp16 (MMA operand)
__device__ float  g_H  [NP * BSZ * 128];  // h, fp32 (epilogue operand)
__device__ __half g_Hr [NP * BSZ * 128];  // h, fp16 (MMA operand)
__device__ __half g_WpT[896 * 512];       // W^T col-permuted, [n][k]
__device__ __half g_U2T[128 * 512];       // [Umat;w_ij]^T, [n][k]
__device__ float  g_bP [896];             // permuted bias
__device__ __half g_A2 [8192 * 384];      // GEMM2 A (r*h parts)
__device__ float  g_Z  [8192 * 512];      // softmaxed gates [m][u*4+g]

__device__ __forceinline__ void mma16(float* c, const uint32_t* a, uint32_t b0, uint32_t b1) {
    asm volatile("mma.sync.aligned.m16n8k16.row.col.f32.f16.f16.f32 "
        "{%0,%1,%2,%3},{%4,%5,%6,%7},{%8,%9},{%0,%1,%2,%3};"
        : "+f"(c[0]), "+f"(c[1]), "+f"(c[2]), "+f"(c[3])
        : "r"(a[0]), "r"(a[1]), "r"(a[2]), "r"(a[3]), "r"(b0), "r"(b1));
}
__device__ __forceinline__ void cp16(uint32_t dst, const void* src, int sz) {
    asm volatile("cp.async.cg.shared.global [%0], [%1], 16, %2;" :: "r"(dst), "l"(src), "r"(sz));
}
__device__ __forceinline__ void ldsm4(uint32_t* r, uint32_t a) {
    asm volatile("ldmatrix.sync.aligned.m8n8.x4.shared.b16 {%0,%1,%2,%3}, [%4];"
        : "=r"(r[0]), "=r"(r[1]), "=r"(r[2]), "=r"(r[3]) : "r"(a));
}
__device__ __forceinline__ void ldsm2(uint32_t* r, uint32_t a) {
    asm volatile("ldmatrix.sync.aligned.m8n8.x2.shared.b16 {%0,%1}, [%2];"
        : "=r"(r[0]), "=r"(r[1]) : "r"(a));
}
__device__ __forceinline__ void pdl_wait() {
    asm volatile("griddepcontrol.wait;" ::: "memory");
}
__device__ __forceinline__ void pdl_trigger() {
    asm volatile("griddepcontrol.launch_dependents;" ::: "memory");
}

// ---------------------------------------------------------------------------
// setup (2 launches)
__global__ void transpose_kernel(const float* __restrict__ in) {
    __shared__ float tile[32][33];
    int x  = blockIdx.x * 32 + threadIdx.x;   // p
    int y0 = blockIdx.y * 32;                 // bc
#pragma unroll
    for (int r = 0; r < 4; r++) {
        int y = y0 + threadIdx.y + r * 8;
        tile[threadIdx.y + r * 8][threadIdx.x] = in[(size_t)y * 1024 + x];
    }
    __syncthreads();
    int xo  = blockIdx.y * 32 + threadIdx.x;
    int yo0 = blockIdx.x * 32;
#pragma unroll
    for (int r = 0; r < 4; r++) {
        int yo = yo0 + threadIdx.y + r * 8;
        g_Th[(size_t)yo * 32768 + xo] = __float2half_rn(tile[threadIdx.x][threadIdx.y + r * 8]);
    }
}

#define NWT (896 * 512)
#define NUT (128 * 512)
__global__ void prep_all_kernel(const float* __restrict__ W, const float* __restrict__ Umat,
                                const float* __restrict__ w_ij, const float* __restrict__ bias) {
    int idx = blockIdx.x * 256 + threadIdx.x;
    if (idx < NWT) {
        int n = idx >> 9, k = idx & 511;
        int corig = (n < 384) ? n : 384 + ((n - 384) & 3) * 128 + ((n - 384) >> 2);
        g_WpT[idx] = __float2half_rn(W[(size_t)k * 896 + corig]);
    } else if (idx < NWT + NUT) {
        int t = idx - NWT;
        int n = t >> 9, k = t & 511;
        g_U2T[t] = __float2half_rn((k < 384) ? Umat[k * 128 + n] : w_ij[(k - 384) * 128 + n]);
    } else if (idx < NWT + NUT + 896) {
        int c = idx - NWT - NUT;
        if (c < 384) g_bP[c] = bias[c];
        else {
            int cc = c - 384, u = cc >> 2, g = cc & 3;
            g_bP[c] = bias[384 + g * 128 + u];
        }
    }
}

// ---------------------------------------------------------------------------
#define STRH  72
#define AHALF (128 * STRH)
#define STGH  (2 * AHALF)
#define SMEM_BYTES (2 * STGH * 2)      // 73728

#define MMA_TILE(aB_)  do {                                                     \
        const uint32_t bBv_ = (aB_) + AHALF * 2;                                \
        _Pragma("unroll")                                                       \
        for (int k16 = 0; k16 < 4; k16++) {                                     \
            const uint32_t kb2 = k16 * 32;                                      \
            uint32_t af0[4], af1[4];                                            \
            ldsm4(af0, (aB_) + aOff0 + kb2);                                    \
            ldsm4(af1, (aB_) + aOff1 + kb2);                                    \
            _Pragma("unroll")                                                   \
            for (int nt = 0; nt < 4; nt++) {                                    \
                uint32_t bf[2];                                                 \
                ldsm2(bf, bBv_ + bOff + nt * (8 * STRH * 2) + kb2);             \
                mma16(acc[0][nt], af0, bf[0], bf[1]);                           \
                mma16(acc[1][nt], af1, bf[0], bf[1]);                           \
            }                                                                   \
        }                                                                       \
    } while (0)

// K1: rz = q @ Wp ; gate epilogue. grid = (7 ntiles, nc*2 mtiles), 512 thr.
// K-order permuted: stages 0,1 = s_ij segment (independent of recurrence).
__global__ __launch_bounds__(NTHR) void k1_kernel(int d) {
    extern __shared__ __half sm[];
    const uint32_t smA0 = (uint32_t)__cvta_generic_to_shared(sm);

    const int tid = threadIdx.x, lane = tid & 31, warp = tid >> 5;
    const int wm = warp >> 2, wn = warp & 3, qj = lane & 3, ql = lane >> 2;
    const int i0 = (d > 31) ? d - 31 : 0;
    const int Mbase = blockIdx.y * 128;
    const int cell = Mbase >> 8, b0 = Mbase & 255;
    const int i = i0 + cell, j = d - i, p = i * 32 + j;
    const int nc0 = blockIdx.x * 128;

    const int l15 = lane & 15, lhi = lane >> 4;
    const uint32_t aOff0 = ((wm * 32 + l15) * STRH + lhi * 8) * 2;
    const uint32_t aOff1 = aOff0 + 16 * STRH * 2;
    const uint32_t bOff  = ((wn * 32 + (lane & 7)) * STRH + ((lane >> 3) & 1) * 8) * 2;

    const __half* src[4]; int vld[4];
    vld[0] = (i > 0) ? 16 : 0;
    vld[1] = (j > 0) ? 16 : 0;
    vld[2] = (i > 0 && j > 0) ? 16 : 0;
    vld[3] = 16;
    src[0] = vld[0] ? g_Hr + ((size_t)(p - 32) * BSZ + b0) * 128 : g_Th;
    src[1] = vld[1] ? g_Hr + ((size_t)(p - 1 ) * BSZ + b0) * 128 : g_Th;
    src[2] = vld[2] ? g_Hr + ((size_t)(p - 33) * BSZ + b0) * 128 : g_Th;
    src[3] = g_Th + ((size_t)p * BSZ + b0) * 128;

    float acc[2][4][4] = {};

    // stage t: seg = (t>>1)==0 ? 3 : (t>>1)-1 ; k_off within seg = (t&1)*64
#define STAGE1(t, buf) do {                                                     \
        int ps_ = (t) >> 1;                                                     \
        int seg_ = (ps_ == 0) ? 3 : ps_ - 1;                                    \
        const __half* sp_ = src[seg_]; int v_ = vld[seg_];                      \
        int kof_ = ((t) & 1) * 64;                                              \
        uint32_t aB_ = smA0 + (buf) * (STGH * 2);                               \
        uint32_t bB_ = aB_ + AHALF * 2;                                         \
        _Pragma("unroll")                                                       \
        for (int r_ = 0; r_ < 2; r_++) {                                        \
            int ix_ = tid + r_ * NTHR;                                          \
            int m_ = ix_ >> 3, c_ = ix_ & 7;                                    \
            cp16(aB_ + (m_ * STRH + c_ * 8) * 2,                                \
                 sp_ + (size_t)m_ * 128 + kof_ + c_ * 8, v_);                   \
        }                                                                       \
        const __half* wp_ = g_WpT + (size_t)nc0 * 512 + seg_ * 128 + kof_;      \
        _Pragma("unroll")                                                       \
        for (int r_ = 0; r_ < 2; r_++) {                                        \
            int ix_ = tid + r_ * NTHR;                                          \
            int n_ = ix_ >> 3, c_ = ix_ & 7;                                    \
            cp16(bB_ + (n_ * STRH + c_ * 8) * 2,                                \
                 wp_ + (size_t)n_ * 512 + c_ * 8, 16);                          \
        }                                                                       \
        asm volatile("cp.async.commit_group;");                                 \
    } while (0)

    // stages 0,1 touch only g_Th/g_WpT -> issue before grid-dependency wait
    STAGE1(0, 0);
    STAGE1(1, 1);
    pdl_wait();
#pragma unroll 1
    for (int t = 0; t < 8; t++) {
        if (t < 7) asm volatile("cp.async.wait_group 1;");
        else       asm volatile("cp.async.wait_group 0;");
        __syncthreads();
        const uint32_t aB = smA0 + (t & 1) * (STGH * 2);
        MMA_TILE(aB);
        __syncthreads();
        if (t < 6) STAGE1(t + 2, t & 1);
    }
    pdl_trigger();

    // ---- epilogue ----
    if (nc0 < 384) {
        const float* hsrc[3];
        hsrc[0] = (j > 0)          ? g_H + ((size_t)(p - 1 ) * BSZ + b0) * 128 : nullptr;
        hsrc[1] = (i > 0)          ? g_H + ((size_t)(p - 32) * BSZ + b0) * 128 : nullptr;
        hsrc[2] = (i > 0 && j > 0) ? g_H + ((size_t)(p - 33) * BSZ + b0) * 128 : nullptr;
#pragma unroll
        for (int mt = 0; mt < 2; mt++) {
#pragma unroll
            for (int half = 0; half < 2; half++) {
                int lr = wm * 32 + mt * 16 + ql + half * 8;
                int Mr = Mbase + lr;
#pragma unroll
                for (int nt = 0; nt < 4; nt++) {
                    int c = nc0 + wn * 32 + nt * 8 + 2 * qj;
                    float v0 = acc[mt][nt][half * 2 + 0] + g_bP[c];
                    float v1 = acc[mt][nt][half * 2 + 1] + g_bP[c + 1];
                    v0 = fminf(fmaxf(0.2f * v0 + 0.5f, 0.f), 1.f);
                    v1 = fminf(fmaxf(0.2f * v1 + 0.5f, 0.f), 1.f);
                    int seg = c >> 7, u = c & 127;
                    const float* hp = hsrc[seg];
                    float h0 = hp ? hp[lr * 128 + u]     : 0.f;
                    float h1 = hp ? hp[lr * 128 + u + 1] : 0.f;
                    *(__half2*)&g_A2[(size_t)Mr * 384 + c] =
                        __floats2half2_rn(v0 * h0, v1 * h1);
                }
            }
        }
    } else {
#pragma unroll
        for (int mt = 0; mt < 2; mt++) {
#pragma unroll
            for (int half = 0; half < 2; half++) {
                int lr = wm * 32 + mt * 16 + ql + half * 8;
                int Mr = Mbase + lr;
#pragma unroll
                for (int nt = 0; nt < 4; nt++) {
                    int c = nc0 + wn * 32 + nt * 8 + 2 * qj;
                    float z0 = acc[mt][nt][half * 2 + 0] + g_bP[c];
                    float z1 = acc[mt][nt][half * 2 + 1] + g_bP[c + 1];
                    float q0 = __shfl_xor_sync(0xffffffffu, z0, 1);
                    float q1 = __shfl_xor_sync(0xffffffffu, z1, 1);
                    float mx = fmaxf(fmaxf(z0, z1), fmaxf(q0, q1));
                    float e0 = __expf(z0 - mx), e1 = __expf(z1 - mx);
                    float s2 = e0 + e1;
                    float st = s2 + __shfl_xor_sync(0xffffffffu, s2, 1);
                    float inv = 1.f / st;
                    int cc = c - 384, u = cc >> 2, g = cc & 3;
                    *(float2*)&g_Z[(size_t)Mr * 512 + u * 4 + g] =
                        make_float2(e0 * inv, e1 * inv);
                }
            }
        }
    }
}

// K2: hstar = tanh(A2 @ U2 + b_ij); epilogue blends with gates.
// K-order permuted: stages 0,1 = s_ij segment (g_Th, independent).
__global__ __launch_bounds__(NTHR) void k2_kernel(int d, const float* __restrict__ bias,
                                                  float* __restrict__ out) {
    extern __shared__ __half sm[];
    const uint32_t smA0 = (uint32_t)__cvta_generic_to_shared(sm);

    const int tid = threadIdx.x, lane = tid & 31, warp = tid >> 5;
    const int wm = warp >> 2, wn = warp & 3, qj = lane & 3, ql = lane >> 2;
    const int i0 = (d > 31) ? d - 31 : 0;
    const int Mbase = blockIdx.x * 128;
    const int cell = Mbase >> 8, b0 = Mbase & 255;
    const int i = i0 + cell, j = d - i, p = i * 32 + j;

    const int l15 = lane & 15, lhi = lane >> 4;
    const uint32_t aOff0 = ((wm * 32 + l15) * STRH + lhi * 8) * 2;
    const uint32_t aOff1 = aOff0 + 16 * STRH * 2;
    const uint32_t bOff  = ((wn * 32 + (lane & 7)) * STRH + ((lane >> 3) & 1) * 8) * 2;

    const __half* Tsrc = g_Th + ((size_t)p * BSZ + b0) * 128;
    float acc[2][4][4] = {};

    // stage t: t<2 -> Tsrc k_off t*64, U2T rows 384+t*64 ; t>=2 -> A2 (t-2)*64
#define STAGE2(t, buf) do {                                                     \
        uint32_t aB_ = smA0 + (buf) * (STGH * 2);                               \
        uint32_t bB_ = aB_ + AHALF * 2;                                         \
        _Pragma("unroll")                                                       \
        for (int r_ = 0; r_ < 2; r_++) {                                        \
            int ix_ = tid + r_ * NTHR;                                          \
            int m_ = ix_ >> 3, c_ = ix_ & 7;                                    \
            const __half* sp_;                                                  \
            if ((t) < 2) sp_ = Tsrc + (size_t)m_ * 128 + (t) * 64 + c_ * 8;             \
            else         sp_ = g_A2 + (size_t)(Mbase + m_) * 384 + ((t) - 2) * 64 + c_ * 8; \
            cp16(aB_ + (m_ * STRH + c_ * 8) * 2, sp_, 16);                      \
        }                                                                       \
        const __half* up_ = g_U2T + (((t) < 2) ? (384 + (t) * 64) : (((t) - 2) * 64)); \
        _Pragma("unroll")                                                       \
        for (int r_ = 0; r_ < 2; r_++) {                                        \
            int ix_ = tid + r_ * NTHR;                                          \
            int n_ = ix_ >> 3, c_ = ix_ & 7;                                    \
            cp16(bB_ + (n_ * STRH + c_ * 8) * 2,                                \
                 up_ + (size_t)n_ * 512 + c_ * 8, 16);                          \
        }                                                                       \
        asm volatile("cp.async.commit_group;");                                 \
    } while (0)

    STAGE2(0, 0);
    STAGE2(1, 1);
    pdl_wait();
#pragma unroll 1
    for (int t = 0; t < 8; t++) {
        if (t < 7) asm volatile("cp.async.wait_group 1;");
        else       asm volatile("cp.async.wait_group 0;");
        __syncthreads();
        const uint32_t aB = smA0 + (t & 1) * (STGH * 2);
        MMA_TILE(aB);
        __syncthreads();
        if (t < 6) STAGE2(t + 2, t & 1);
    }
    pdl_trigger();

    const float* hL = (j > 0)          ? g_H + ((size_t)(p - 1 ) * BSZ + b0) * 128 : nullptr;
    const float* hT = (i > 0)          ? g_H + ((size_t)(p - 32) * BSZ + b0) * 128 : nullptr;
    const float* hD = (i > 0 && j > 0) ? g_H + ((size_t)(p - 33) * BSZ + b0) * 128 : nullptr;
    float*  Hd  = g_H  + ((size_t)p * BSZ + b0) * 128;
    __half* Hrd = g_Hr + ((size_t)p * BSZ + b0) * 128;

#pragma unroll
    for (int mt = 0; mt < 2; mt++) {
#pragma unroll
        for (int half = 0; half < 2; half++) {
            int lr = wm * 32 + mt * 16 + ql + half * 8;
            int Mr = Mbase + lr;
#pragma unroll
            for (int nt = 0; nt < 4; nt++) {
                int u = wn * 32 + nt * 8 + 2 * qj;
                float a0 = acc[mt][nt][half * 2 + 0] + bias[896 + u];
                float a1 = acc[mt][nt][half * 2 + 1] + bias[896 + u + 1];
                float hs0 = tanhf(a0), hs1 = tanhf(a1);
                float4 z0 = *(const float4*)&g_Z[(size_t)Mr * 512 + u * 4];
                float4 z1 = *(const float4*)&g_Z[(size_t)Mr * 512 + (u + 1) * 4];
                float l0 = hL ? hL[lr * 128 + u] : 0.f, l1 = hL ? hL[lr * 128 + u + 1] : 0.f;
                float t0 = hT ? hT[lr * 128 + u] : 0.f, t1 = hT ? hT[lr * 128 + u + 1] : 0.f;
                float d0 = hD ? hD[lr * 128 + u] : 0.f, d1 = hD ? hD[lr * 128 + u + 1] : 0.f;
                float h0 = z0.y * l0 + z0.z * t0 + z0.w * d0 + z0.x * hs0;
                float h1 = z1.y * l1 + z1.z * t1 + z1.w * d1 + z1.x * hs1;
                *(float2*)&Hd[lr * 128 + u]   = make_float2(h0, h1);
                *(__half2*)&Hrd[lr * 128 + u] = __floats2half2_rn(h0, h1);
                if (p == 1023)
                    *(float2*)&out[(size_t)(b0 + lr) * 128 + u] = make_float2(h0, h1);
            }
        }
    }
}

// ---------------------------------------------------------------------------
extern "C" void kernel_launch(void* const* d_in, const int* in_sizes, int n_in,
                              void* d_out, int out_size) {
    const float* inputs = (const float*)d_in[0];
    const float* W      = (const float*)d_in[1];
    const float* Umat   = (const float*)d_in[2];
    const float* bias   = (const float*)d_in[3];
    const float* w_ij   = (const float*)d_in[4];
    float* out = (float*)d_out;

    cudaFuncSetAttribute(k1_kernel, cudaFuncAttributeMaxDynamicSharedMemorySize, SMEM_BYTES);
    cudaFuncSetAttribute(k2_kernel, cudaFuncAttributeMaxDynamicSharedMemorySize, SMEM_BYTES);

    transpose_kernel<<<dim3(32, 1024), dim3(32, 8)>>>(inputs);
    prep_all_kernel<<<(NWT + NUT + 896 + 255) / 256, 256>>>(W, Umat, w_ij, bias);

    cudaLaunchAttribute attrs[1];
    attrs[0].id = cudaLaunchAttributeProgrammaticStreamSerialization;
    attrs[0].val.programmaticStreamSerializationAllowed = 1;

    for (int d = 0; d <= 62; d++) {
        int i0 = (d > 31) ? d - 31 : 0;
        int i1 = (d < 31) ? d : 31;
        int nc = i1 - i0 + 1;

        if (d == 0) {
            // first diagonal: plain launch (pre-sync stages would race with setup)
            k1_kernel<<<dim3(7, nc * 2), NTHR, SMEM_BYTES>>>(d);
        } else {
            cudaLaunchConfig_t c1 = {};
            c1.gridDim = dim3(7, nc * 2); c1.blockDim = dim3(NTHR);
            c1.dynamicSmemBytes = SMEM_BYTES; c1.stream = 0;
            c1.attrs = attrs; c1.numAttrs = 1;
            cudaLaunchKernelEx(&c1, k1_kernel, d);
        }
        cudaLaunchConfig_t c2 = {};
        c2.gridDim = dim3(nc * 2); c2.blockDim = dim3(NTHR);
        c2.dynamicSmemBytes = SMEM_BYTES; c2.stream = 0;
        c2.attrs = attrs; c2.numAttrs = 1;
        cudaLaunchKernelEx(&c2, k2_kernel, d, bias, out);
    }
    (void)in_sizes; (void)n_in; (void)out_size;
}

// round 13
// speedup vs baseline: 1.2908x; 1.0475x over previous
#include <cuda_runtime.h>
#include <cuda_fp16.h>
#include <cstdint>
#include <math.h>

// SpatialGRU: B=256, C=128, L1=L2=32, U=128
// R12 (R9 kernels + PDL) with pdl_wait moved AFTER the first 2 MMA k-iters:
// iterations 0-1 consume only recurrence-independent data (s_ij + weights),
// so each kernel overlaps ~2 k-iters of tensor work with its predecessor's tail.

#define NP  1024
#define BSZ 256
#define NTHR 512

// ---- device scratch (no allocation allowed) ----
__device__ __half g_Th [NP * BSZ * 128];  // s, fp16 (MMA operand)
__device__ float  g_H  [NP * BSZ * 128];  // h, fp32 (epilogue operand)
__device__ __half g_Hr [NP * BSZ * 128];  // h, fp16 (MMA operand)
__device__ __half g_WpT[896 * 512];       // W^T col-permuted, [n][k]
__device__ __half g_U2T[128 * 512];       // [Umat;w_ij]^T, [n][k]
__device__ float  g_bP [896];             // permuted bias
__device__ __half g_A2 [8192 * 384];      // GEMM2 A (r*h parts)
__device__ float  g_Z  [8192 * 512];      // softmaxed gates [m][u*4+g]

__device__ __forceinline__ void mma16(float* c, const uint32_t* a, uint32_t b0, uint32_t b1) {
    asm volatile("mma.sync.aligned.m16n8k16.row.col.f32.f16.f16.f32 "
        "{%0,%1,%2,%3},{%4,%5,%6,%7},{%8,%9},{%0,%1,%2,%3};"
        : "+f"(c[0]), "+f"(c[1]), "+f"(c[2]), "+f"(c[3])
        : "r"(a[0]), "r"(a[1]), "r"(a[2]), "r"(a[3]), "r"(b0), "r"(b1));
}
__device__ __forceinline__ void cp16(uint32_t dst, const void* src, int sz) {
    asm volatile("cp.async.cg.shared.global [%0], [%1], 16, %2;" :: "r"(dst), "l"(src), "r"(sz));
}
__device__ __forceinline__ void ldsm4(uint32_t* r, uint32_t a) {
    asm volatile("ldmatrix.sync.aligned.m8n8.x4.shared.b16 {%0,%1,%2,%3}, [%4];"
        : "=r"(r[0]), "=r"(r[1]), "=r"(r[2]), "=r"(r[3]) : "r"(a));
}
__device__ __forceinline__ void ldsm2(uint32_t* r, uint32_t a) {
    asm volatile("ldmatrix.sync.aligned.m8n8.x2.shared.b16 {%0,%1}, [%2];"
        : "=r"(r[0]), "=r"(r[1]) : "r"(a));
}
__device__ __forceinline__ void pdl_wait() {
    asm volatile("griddepcontrol.wait;" ::: "memory");
}
__device__ __forceinline__ void pdl_trigger() {
    asm volatile("griddepcontrol.launch_dependents;" ::: "memory");
}

// ---------------------------------------------------------------------------
// setup (2 launches)
__global__ void transpose_kernel(const float* __restrict__ in) {
    __shared__ float tile[32][33];
    int x  = blockIdx.x * 32 + threadIdx.x;   // p
    int y0 = blockIdx.y * 32;                 // bc
#pragma unroll
    for (int r = 0; r < 4; r++) {
        int y = y0 + threadIdx.y + r * 8;
        tile[threadIdx.y + r * 8][threadIdx.x] = in[(size_t)y * 1024 + x];
    }
    __syncthreads();
    int xo  = blockIdx.y * 32 + threadIdx.x;
    int yo0 = blockIdx.x * 32;
#pragma unroll
    for (int r = 0; r < 4; r++) {
        int yo = yo0 + threadIdx.y + r * 8;
        g_Th[(size_t)yo * 32768 + xo] = __float2half_rn(tile[threadIdx.x][threadIdx.y + r * 8]);
    }
}

#define NWT (896 * 512)
#define NUT (128 * 512)
__global__ void prep_all_kernel(const float* __restrict__ W, const float* __restrict__ Umat,
                                const float* __restrict__ w_ij, const float* __restrict__ bias) {
    int idx = blockIdx.x * 256 + threadIdx.x;
    if (idx < NWT) {
        int n = idx >> 9, k = idx & 511;
        int corig = (n < 384) ? n : 384 + ((n - 384) & 3) * 128 + ((n - 384) >> 2);
        g_WpT[idx] = __float2half_rn(W[(size_t)k * 896 + corig]);
    } else if (idx < NWT + NUT) {
        int t = idx - NWT;
        int n = t >> 9, k = t & 511;
        g_U2T[t] = __float2half_rn((k < 384) ? Umat[k * 128 + n] : w_ij[(k - 384) * 128 + n]);
    } else if (idx < NWT + NUT + 896) {
        int c = idx - NWT - NUT;
        if (c < 384) g_bP[c] = bias[c];
        else {
            int cc = c - 384, u = cc >> 2, g = cc & 3;
            g_bP[c] = bias[384 + g * 128 + u];
        }
    }
}

// ---------------------------------------------------------------------------
#define STRH  72
#define AHALF (128 * STRH)
#define STGH  (2 * AHALF)
#define SMEM_BYTES (2 * STGH * 2)      // 73728

#define MMA_TILE(aB_)  do {                                                     \
        const uint32_t bBv_ = (aB_) + AHALF * 2;                                \
        _Pragma("unroll")                                                       \
        for (int k16 = 0; k16 < 4; k16++) {                                     \
            const uint32_t kb2 = k16 * 32;                                      \
            uint32_t af0[4], af1[4];                                            \
            ldsm4(af0, (aB_) + aOff0 + kb2);                                    \
            ldsm4(af1, (aB_) + aOff1 + kb2);                                    \
            _Pragma("unroll")                                                   \
            for (int nt = 0; nt < 4; nt++) {                                    \
                uint32_t bf[2];                                                 \
                ldsm2(bf, bBv_ + bOff + nt * (8 * STRH * 2) + kb2);             \
                mma16(acc[0][nt], af0, bf[0], bf[1]);                           \
                mma16(acc[1][nt], af1, bf[0], bf[1]);                           \
            }                                                                   \
        }                                                                       \
    } while (0)

// K1: rz = q @ Wp ; gate epilogue. grid = (7 ntiles, nc*2 mtiles), 512 thr.
// K-order permuted: stages 0,1 = s_ij segment (independent of recurrence).
__global__ __launch_bounds__(NTHR) void k1_kernel(int d) {
    extern __shared__ __half sm[];
    const uint32_t smA0 = (uint32_t)__cvta_generic_to_shared(sm);

    const int tid = threadIdx.x, lane = tid & 31, warp = tid >> 5;
    const int wm = warp >> 2, wn = warp & 3, qj = lane & 3, ql = lane >> 2;
    const int i0 = (d > 31) ? d - 31 : 0;
    const int Mbase = blockIdx.y * 128;
    const int cell = Mbase >> 8, b0 = Mbase & 255;
    const int i = i0 + cell, j = d - i, p = i * 32 + j;
    const int nc0 = blockIdx.x * 128;

    const int l15 = lane & 15, lhi = lane >> 4;
    const uint32_t aOff0 = ((wm * 32 + l15) * STRH + lhi * 8) * 2;
    const uint32_t aOff1 = aOff0 + 16 * STRH * 2;
    const uint32_t bOff  = ((wn * 32 + (lane & 7)) * STRH + ((lane >> 3) & 1) * 8) * 2;

    const __half* src[4]; int vld[4];
    vld[0] = (i > 0) ? 16 : 0;
    vld[1] = (j > 0) ? 16 : 0;
    vld[2] = (i > 0 && j > 0) ? 16 : 0;
    vld[3] = 16;
    src[0] = vld[0] ? g_Hr + ((size_t)(p - 32) * BSZ + b0) * 128 : g_Th;
    src[1] = vld[1] ? g_Hr + ((size_t)(p - 1 ) * BSZ + b0) * 128 : g_Th;
    src[2] = vld[2] ? g_Hr + ((size_t)(p - 33) * BSZ + b0) * 128 : g_Th;
    src[3] = g_Th + ((size_t)p * BSZ + b0) * 128;

    float acc[2][4][4] = {};

    // stage t: seg = (t>>1)==0 ? 3 : (t>>1)-1 ; k_off within seg = (t&1)*64
#define STAGE1(t, buf) do {                                                     \
        int ps_ = (t) >> 1;                                                     \
        int seg_ = (ps_ == 0) ? 3 : ps_ - 1;                                    \
        const __half* sp_ = src[seg_]; int v_ = vld[seg_];                      \
        int kof_ = ((t) & 1) * 64;                                              \
        uint32_t aB_ = smA0 + (buf) * (STGH * 2);                               \
        uint32_t bB_ = aB_ + AHALF * 2;                                         \
        _Pragma("unroll")                                                       \
        for (int r_ = 0; r_ < 2; r_++) {                                        \
            int ix_ = tid + r_ * NTHR;                                          \
            int m_ = ix_ >> 3, c_ = ix_ & 7;                                    \
            cp16(aB_ + (m_ * STRH + c_ * 8) * 2,                                \
                 sp_ + (size_t)m_ * 128 + kof_ + c_ * 8, v_);                   \
        }                                                                       \
        const __half* wp_ = g_WpT + (size_t)nc0 * 512 + seg_ * 128 + kof_;      \
        _Pragma("unroll")                                                       \
        for (int r_ = 0; r_ < 2; r_++) {                                        \
            int ix_ = tid + r_ * NTHR;                                          \
            int n_ = ix_ >> 3, c_ = ix_ & 7;                                    \
            cp16(bB_ + (n_ * STRH + c_ * 8) * 2,                                \
                 wp_ + (size_t)n_ * 512 + c_ * 8, 16);                          \
        }                                                                       \
        asm volatile("cp.async.commit_group;");                                 \
    } while (0)

    // stages 0,1 + MMA iters 0,1 touch only setup data -> run BEFORE pdl_wait
    STAGE1(0, 0);
    STAGE1(1, 1);
    asm volatile("cp.async.wait_group 1;");
    __syncthreads();
    MMA_TILE(smA0);                               // iter 0 (buf 0)
    asm volatile("cp.async.wait_group 0;");
    __syncthreads();
    MMA_TILE(smA0 + STGH * 2);                    // iter 1 (buf 1)
    pdl_wait();
    __syncthreads();
    STAGE1(2, 0);
    STAGE1(3, 1);
#pragma unroll 1
    for (int t = 2; t < 8; t++) {
        if (t < 7) asm volatile("cp.async.wait_group 1;");
        else       asm volatile("cp.async.wait_group 0;");
        __syncthreads();
        const uint32_t aB = smA0 + (t & 1) * (STGH * 2);
        MMA_TILE(aB);
        __syncthreads();
        if (t < 6) STAGE1(t + 2, t & 1);
    }
    pdl_trigger();

    // ---- epilogue ----
    if (nc0 < 384) {
        const float* hsrc[3];
        hsrc[0] = (j > 0)          ? g_H + ((size_t)(p - 1 ) * BSZ + b0) * 128 : nullptr;
        hsrc[1] = (i > 0)          ? g_H + ((size_t)(p - 32) * BSZ + b0) * 128 : nullptr;
        hsrc[2] = (i > 0 && j > 0) ? g_H + ((size_t)(p - 33) * BSZ + b0) * 128 : nullptr;
#pragma unroll
        for (int mt = 0; mt < 2; mt++) {
#pragma unroll
            for (int half = 0; half < 2; half++) {
                int lr = wm * 32 + mt * 16 + ql + half * 8;
                int Mr = Mbase + lr;
#pragma unroll
                for (int nt = 0; nt < 4; nt++) {
                    int c = nc0 + wn * 32 + nt * 8 + 2 * qj;
                    float v0 = acc[mt][nt][half * 2 + 0] + g_bP[c];
                    float v1 = acc[mt][nt][half * 2 + 1] + g_bP[c + 1];
                    v0 = fminf(fmaxf(0.2f * v0 + 0.5f, 0.f), 1.f);
                    v1 = fminf(fmaxf(0.2f * v1 + 0.5f, 0.f), 1.f);
                    int seg = c >> 7, u = c & 127;
                    const float* hp = hsrc[seg];
                    float h0 = hp ? hp[lr * 128 + u]     : 0.f;
                    float h1 = hp ? hp[lr * 128 + u + 1] : 0.f;
                    *(__half2*)&g_A2[(size_t)Mr * 384 + c] =
                        __floats2half2_rn(v0 * h0, v1 * h1);
                }
            }
        }
    } else {
#pragma unroll
        for (int mt = 0; mt < 2; mt++) {
#pragma unroll
            for (int half = 0; half < 2; half++) {
                int lr = wm * 32 + mt * 16 + ql + half * 8;
                int Mr = Mbase + lr;
#pragma unroll
                for (int nt = 0; nt < 4; nt++) {
                    int c = nc0 + wn * 32 + nt * 8 + 2 * qj;
                    float z0 = acc[mt][nt][half * 2 + 0] + g_bP[c];
                    float z1 = acc[mt][nt][half * 2 + 1] + g_bP[c + 1];
                    float q0 = __shfl_xor_sync(0xffffffffu, z0, 1);
                    float q1 = __shfl_xor_sync(0xffffffffu, z1, 1);
                    float mx = fmaxf(fmaxf(z0, z1), fmaxf(q0, q1));
                    float e0 = __expf(z0 - mx), e1 = __expf(z1 - mx);
                    float s2 = e0 + e1;
                    float st = s2 + __shfl_xor_sync(0xffffffffu, s2, 1);
                    float inv = 1.f / st;
                    int cc = c - 384, u = cc >> 2, g = cc & 3;
                    *(float2*)&g_Z[(size_t)Mr * 512 + u * 4 + g] =
                        make_float2(e0 * inv, e1 * inv);
                }
            }
        }
    }
}

// K2: hstar = tanh(A2 @ U2 + b_ij); epilogue blends with gates.
// K-order permuted: stages 0,1 = s_ij segment (g_Th, independent).
__global__ __launch_bounds__(NTHR) void k2_kernel(int d, const float* __restrict__ bias,
                                                  float* __restrict__ out) {
    extern __shared__ __half sm[];
    const uint32_t smA0 = (uint32_t)__cvta_generic_to_shared(sm);

    const int tid = threadIdx.x, lane = tid & 31, warp = tid >> 5;
    const int wm = warp >> 2, wn = warp & 3, qj = lane & 3, ql = lane >> 2;
    const int i0 = (d > 31) ? d - 31 : 0;
    const int Mbase = blockIdx.x * 128;
    const int cell = Mbase >> 8, b0 = Mbase & 255;
    const int i = i0 + cell, j = d - i, p = i * 32 + j;

    const int l15 = lane & 15, lhi = lane >> 4;
    const uint32_t aOff0 = ((wm * 32 + l15) * STRH + lhi * 8) * 2;
    const uint32_t aOff1 = aOff0 + 16 * STRH * 2;
    const uint32_t bOff  = ((wn * 32 + (lane & 7)) * STRH + ((lane >> 3) & 1) * 8) * 2;

    const __half* Tsrc = g_Th + ((size_t)p * BSZ + b0) * 128;
    float acc[2][4][4] = {};

    // stage t: t<2 -> Tsrc k_off t*64, U2T rows 384+t*64 ; t>=2 -> A2 (t-2)*64
#define STAGE2(t, buf) do {                                                     \
        uint32_t aB_ = smA0 + (buf) * (STGH * 2);                               \
        uint32_t bB_ = aB_ + AHALF * 2;                                         \
        _Pragma("unroll")                                                       \
        for (int r_ = 0; r_ < 2; r_++) {                                        \
            int ix_ = tid + r_ * NTHR;                                          \
            int m_ = ix_ >> 3, c_ = ix_ & 7;                                    \
            const __half* sp_;                                                  \
            if ((t) < 2) sp_ = Tsrc + (size_t)m_ * 128 + (t) * 64 + c_ * 8;             \
            else         sp_ = g_A2 + (size_t)(Mbase + m_) * 384 + ((t) - 2) * 64 + c_ * 8; \
            cp16(aB_ + (m_ * STRH + c_ * 8) * 2, sp_, 16);                      \
        }                                                                       \
        const __half* up_ = g_U2T + (((t) < 2) ? (384 + (t) * 64) : (((t) - 2) * 64)); \
        _Pragma("unroll")                                                       \
        for (int r_ = 0; r_ < 2; r_++) {                                        \
            int ix_ = tid + r_ * NTHR;                                          \
            int n_ = ix_ >> 3, c_ = ix_ & 7;                                    \
            cp16(bB_ + (n_ * STRH + c_ * 8) * 2,                                \
                 up_ + (size_t)n_ * 512 + c_ * 8, 16);                          \
        }                                                                       \
        asm volatile("cp.async.commit_group;");                                 \
    } while (0)

    // stages 0,1 + MMA iters 0,1 touch only setup data -> run BEFORE pdl_wait
    STAGE2(0, 0);
    STAGE2(1, 1);
    asm volatile("cp.async.wait_group 1;");
    __syncthreads();
    MMA_TILE(smA0);                               // iter 0 (buf 0)
    asm volatile("cp.async.wait_group 0;");
    __syncthreads();
    MMA_TILE(smA0 + STGH * 2);                    // iter 1 (buf 1)
    pdl_wait();
    __syncthreads();
    STAGE2(2, 0);
    STAGE2(3, 1);
#pragma unroll 1
    for (int t = 2; t < 8; t++) {
        if (t < 7) asm volatile("cp.async.wait_group 1;");
        else       asm volatile("cp.async.wait_group 0;");
        __syncthreads();
        const uint32_t aB = smA0 + (t & 1) * (STGH * 2);
        MMA_TILE(aB);
        __syncthreads();
        if (t < 6) STAGE2(t + 2, t & 1);
    }
    pdl_trigger();

    const float* hL = (j > 0)          ? g_H + ((size_t)(p - 1 ) * BSZ + b0) * 128 : nullptr;
    const float* hT = (i > 0)          ? g_H + ((size_t)(p - 32) * BSZ + b0) * 128 : nullptr;
    const float* hD = (i > 0 && j > 0) ? g_H + ((size_t)(p - 33) * BSZ + b0) * 128 : nullptr;
    float*  Hd  = g_H  + ((size_t)p * BSZ + b0) * 128;
    __half* Hrd = g_Hr + ((size_t)p * BSZ + b0) * 128;

#pragma unroll
    for (int mt = 0; mt < 2; mt++) {
#pragma unroll
        for (int half = 0; half < 2; half++) {
            int lr = wm * 32 + mt * 16 + ql + half * 8;
            int Mr = Mbase + lr;
#pragma unroll
            for (int nt = 0; nt < 4; nt++) {
                int u = wn * 32 + nt * 8 + 2 * qj;
                float a0 = acc[mt][nt][half * 2 + 0] + bias[896 + u];
                float a1 = acc[mt][nt][half * 2 + 1] + bias[896 + u + 1];
                float hs0 = tanhf(a0), hs1 = tanhf(a1);
                float4 z0 = *(const float4*)&g_Z[(size_t)Mr * 512 + u * 4];
                float4 z1 = *(const float4*)&g_Z[(size_t)Mr * 512 + (u + 1) * 4];
                float l0 = hL ? hL[lr * 128 + u] : 0.f, l1 = hL ? hL[lr * 128 + u + 1] : 0.f;
                float t0 = hT ? hT[lr * 128 + u] : 0.f, t1 = hT ? hT[lr * 128 + u + 1] : 0.f;
                float d0 = hD ? hD[lr * 128 + u] : 0.f, d1 = hD ? hD[lr * 128 + u + 1] : 0.f;
                float h0 = z0.y * l0 + z0.z * t0 + z0.w * d0 + z0.x * hs0;
                float h1 = z1.y * l1 + z1.z * t1 + z1.w * d1 + z1.x * hs1;
                *(float2*)&Hd[lr * 128 + u]   = make_float2(h0, h1);
                *(__half2*)&Hrd[lr * 128 + u] = __floats2half2_rn(h0, h1);
                if (p == 1023)
                    *(float2*)&out[(size_t)(b0 + lr) * 128 + u] = make_float2(h0, h1);
            }
        }
    }
}

// ---------------------------------------------------------------------------
extern "C" void kernel_launch(void* const* d_in, const int* in_sizes, int n_in,
                              void* d_out, int out_size) {
    const float* inputs = (const float*)d_in[0];
    const float* W      = (const float*)d_in[1];
    const float* Umat   = (const float*)d_in[2];
    const float* bias   = (const float*)d_in[3];
    const float* w_ij   = (const float*)d_in[4];
    float* out = (float*)d_out;

    cudaFuncSetAttribute(k1_kernel, cudaFuncAttributeMaxDynamicSharedMemorySize, SMEM_BYTES);
    cudaFuncSetAttribute(k2_kernel, cudaFuncAttributeMaxDynamicSharedMemorySize, SMEM_BYTES);

    transpose_kernel<<<dim3(32, 1024), dim3(32, 8)>>>(inputs);
    prep_all_kernel<<<(NWT + NUT + 896 + 255) / 256, 256>>>(W, Umat, w_ij, bias);

    cudaLaunchAttribute attrs[1];
    attrs[0].id = cudaLaunchAttributeProgrammaticStreamSerialization;
    attrs[0].val.programmaticStreamSerializationAllowed = 1;

    for (int d = 0; d <= 62; d++) {
        int i0 = (d > 31) ? d - 31 : 0;
        int i1 = (d < 31) ? d : 31;
        int nc = i1 - i0 + 1;

        if (d == 0) {
            // first diagonal: plain launch (pre-sync stages would race with setup)
            k1_kernel<<<dim3(7, nc * 2), NTHR, SMEM_BYTES>>>(d);
        } else {
            cudaLaunchConfig_t c1 = {};
            c1.gridDim = dim3(7, nc * 2); c1.blockDim = dim3(NTHR);
            c1.dynamicSmemBytes = SMEM_BYTES; c1.stream = 0;
            c1.attrs = attrs; c1.numAttrs = 1;
            cudaLaunchKernelEx(&c1, k1_kernel, d);
        }
        cudaLaunchConfig_t c2 = {};
        c2.gridDim = dim3(nc * 2); c2.blockDim = dim3(NTHR);
        c2.dynamicSmemBytes = SMEM_BYTES; c2.stream = 0;
        c2.attrs = attrs; c2.numAttrs = 1;
        cudaLaunchKernelEx(&c2, k2_kernel, d, bias, out);
    }
    (void)in_sizes; (void)n_in; (void)out_size;
}

// round 14
// speedup vs baseline: 1.4605x; 1.1314x over previous
#include <cuda_runtime.h>
#include <cuda_fp16.h>
#include <cstdint>
#include <math.h>

// SpatialGRU: B=256, C=128, L1=L2=32, U=128
// R13 (PDL, pre-wait MMA iters) + k2 M-split: k2 tiles are 64x128x512,
// grid nc*4, 512 thr, 4x4 warp grid of 16x32 warp tiles.

#define NP  1024
#define BSZ 256
#define NTHR 512

// ---- device scratch (no allocation allowed) ----
__device__ __half g_Th [NP * BSZ * 128];  // s, fp16 (MMA operand)
__device__ float  g_H  [NP * BSZ * 128];  // h, fp32 (epilogue operand)
__device__ __half g_Hr [NP * BSZ * 128];  // h, fp16 (MMA operand)
__device__ __half g_WpT[896 * 512];       // W^T col-permuted, [n][k]
__device__ __half g_U2T[128 * 512];       // [Umat;w_ij]^T, [n][k]
__device__ float  g_bP [896];             // permuted bias
__device__ __half g_A2 [8192 * 384];      // GEMM2 A (r*h parts)
__device__ float  g_Z  [8192 * 512];      // softmaxed gates [m][u*4+g]

__device__ __forceinline__ void mma16(float* c, const uint32_t* a, uint32_t b0, uint32_t b1) {
    asm volatile("mma.sync.aligned.m16n8k16.row.col.f32.f16.f16.f32 "
        "{%0,%1,%2,%3},{%4,%5,%6,%7},{%8,%9},{%0,%1,%2,%3};"
        : "+f"(c[0]), "+f"(c[1]), "+f"(c[2]), "+f"(c[3])
        : "r"(a[0]), "r"(a[1]), "r"(a[2]), "r"(a[3]), "r"(b0), "r"(b1));
}
__device__ __forceinline__ void cp16(uint32_t dst, const void* src, int sz) {
    asm volatile("cp.async.cg.shared.global [%0], [%1], 16, %2;" :: "r"(dst), "l"(src), "r"(sz));
}
__device__ __forceinline__ void ldsm4(uint32_t* r, uint32_t a) {
    asm volatile("ldmatrix.sync.aligned.m8n8.x4.shared.b16 {%0,%1,%2,%3}, [%4];"
        : "=r"(r[0]), "=r"(r[1]), "=r"(r[2]), "=r"(r[3]) : "r"(a));
}
__device__ __forceinline__ void ldsm2(uint32_t* r, uint32_t a) {
    asm volatile("ldmatrix.sync.aligned.m8n8.x2.shared.b16 {%0,%1}, [%2];"
        : "=r"(r[0]), "=r"(r[1]) : "r"(a));
}
__device__ __forceinline__ void pdl_wait() {
    asm volatile("griddepcontrol.wait;" ::: "memory");
}
__device__ __forceinline__ void pdl_trigger() {
    asm volatile("griddepcontrol.launch_dependents;" ::: "memory");
}

// ---------------------------------------------------------------------------
// setup (2 launches)
__global__ void transpose_kernel(const float* __restrict__ in) {
    __shared__ float tile[32][33];
    int x  = blockIdx.x * 32 + threadIdx.x;   // p
    int y0 = blockIdx.y * 32;                 // bc
#pragma unroll
    for (int r = 0; r < 4; r++) {
        int y = y0 + threadIdx.y + r * 8;
        tile[threadIdx.y + r * 8][threadIdx.x] = in[(size_t)y * 1024 + x];
    }
    __syncthreads();
    int xo  = blockIdx.y * 32 + threadIdx.x;
    int yo0 = blockIdx.x * 32;
#pragma unroll
    for (int r = 0; r < 4; r++) {
        int yo = yo0 + threadIdx.y + r * 8;
        g_Th[(size_t)yo * 32768 + xo] = __float2half_rn(tile[threadIdx.x][threadIdx.y + r * 8]);
    }
}

#define NWT (896 * 512)
#define NUT (128 * 512)
__global__ void prep_all_kernel(const float* __restrict__ W, const float* __restrict__ Umat,
                                const float* __restrict__ w_ij, const float* __restrict__ bias) {
    int idx = blockIdx.x * 256 + threadIdx.x;
    if (idx < NWT) {
        int n = idx >> 9, k = idx & 511;
        int corig = (n < 384) ? n : 384 + ((n - 384) & 3) * 128 + ((n - 384) >> 2);
        g_WpT[idx] = __float2half_rn(W[(size_t)k * 896 + corig]);
    } else if (idx < NWT + NUT) {
        int t = idx - NWT;
        int n = t >> 9, k = t & 511;
        g_U2T[t] = __float2half_rn((k < 384) ? Umat[k * 128 + n] : w_ij[(k - 384) * 128 + n]);
    } else if (idx < NWT + NUT + 896) {
        int c = idx - NWT - NUT;
        if (c < 384) g_bP[c] = bias[c];
        else {
            int cc = c - 384, u = cc >> 2, g = cc & 3;
            g_bP[c] = bias[384 + g * 128 + u];
        }
    }
}

// ---------------------------------------------------------------------------
#define STRH  72
#define AHALF (128 * STRH)
#define STGH  (2 * AHALF)
#define SMEM1 (2 * STGH * 2)           // 73728 (k1)

#define MMA_TILE(aB_)  do {                                                     \
        const uint32_t bBv_ = (aB_) + AHALF * 2;                                \
        _Pragma("unroll")                                                       \
        for (int k16 = 0; k16 < 4; k16++) {                                     \
            const uint32_t kb2 = k16 * 32;                                      \
            uint32_t af0[4], af1[4];                                            \
            ldsm4(af0, (aB_) + aOff0 + kb2);                                    \
            ldsm4(af1, (aB_) + aOff1 + kb2);                                    \
            _Pragma("unroll")                                                   \
            for (int nt = 0; nt < 4; nt++) {                                    \
                uint32_t bf[2];                                                 \
                ldsm2(bf, bBv_ + bOff + nt * (8 * STRH * 2) + kb2);             \
                mma16(acc[0][nt], af0, bf[0], bf[1]);                           \
                mma16(acc[1][nt], af1, bf[0], bf[1]);                           \
            }                                                                   \
        }                                                                       \
    } while (0)

// K1: rz = q @ Wp ; gate epilogue. grid = (7 ntiles, nc*2 mtiles), 512 thr.
// K-order permuted: stages 0,1 = s_ij segment (independent of recurrence).
__global__ __launch_bounds__(NTHR) void k1_kernel(int d) {
    extern __shared__ __half sm[];
    const uint32_t smA0 = (uint32_t)__cvta_generic_to_shared(sm);

    const int tid = threadIdx.x, lane = tid & 31, warp = tid >> 5;
    const int wm = warp >> 2, wn = warp & 3, qj = lane & 3, ql = lane >> 2;
    const int i0 = (d > 31) ? d - 31 : 0;
    const int Mbase = blockIdx.y * 128;
    const int cell = Mbase >> 8, b0 = Mbase & 255;
    const int i = i0 + cell, j = d - i, p = i * 32 + j;
    const int nc0 = blockIdx.x * 128;

    const int l15 = lane & 15, lhi = lane >> 4;
    const uint32_t aOff0 = ((wm * 32 + l15) * STRH + lhi * 8) * 2;
    const uint32_t aOff1 = aOff0 + 16 * STRH * 2;
    const uint32_t bOff  = ((wn * 32 + (lane & 7)) * STRH + ((lane >> 3) & 1) * 8) * 2;

    const __half* src[4]; int vld[4];
    vld[0] = (i > 0) ? 16 : 0;
    vld[1] = (j > 0) ? 16 : 0;
    vld[2] = (i > 0 && j > 0) ? 16 : 0;
    vld[3] = 16;
    src[0] = vld[0] ? g_Hr + ((size_t)(p - 32) * BSZ + b0) * 128 : g_Th;
    src[1] = vld[1] ? g_Hr + ((size_t)(p - 1 ) * BSZ + b0) * 128 : g_Th;
    src[2] = vld[2] ? g_Hr + ((size_t)(p - 33) * BSZ + b0) * 128 : g_Th;
    src[3] = g_Th + ((size_t)p * BSZ + b0) * 128;

    float acc[2][4][4] = {};

    // stage t: seg = (t>>1)==0 ? 3 : (t>>1)-1 ; k_off within seg = (t&1)*64
#define STAGE1(t, buf) do {                                                     \
        int ps_ = (t) >> 1;                                                     \
        int seg_ = (ps_ == 0) ? 3 : ps_ - 1;                                    \
        const __half* sp_ = src[seg_]; int v_ = vld[seg_];                      \
        int kof_ = ((t) & 1) * 64;                                              \
        uint32_t aB_ = smA0 + (buf) * (STGH * 2);                               \
        uint32_t bB_ = aB_ + AHALF * 2;                                         \
        _Pragma("unroll")                                                       \
        for (int r_ = 0; r_ < 2; r_++) {                                        \
            int ix_ = tid + r_ * NTHR;                                          \
            int m_ = ix_ >> 3, c_ = ix_ & 7;                                    \
            cp16(aB_ + (m_ * STRH + c_ * 8) * 2,                                \
                 sp_ + (size_t)m_ * 128 + kof_ + c_ * 8, v_);                   \
        }                                                                       \
        const __half* wp_ = g_WpT + (size_t)nc0 * 512 + seg_ * 128 + kof_;      \
        _Pragma("unroll")                                                       \
        for (int r_ = 0; r_ < 2; r_++) {                                        \
            int ix_ = tid + r_ * NTHR;                                          \
            int n_ = ix_ >> 3, c_ = ix_ & 7;                                    \
            cp16(bB_ + (n_ * STRH + c_ * 8) * 2,                                \
                 wp_ + (size_t)n_ * 512 + c_ * 8, 16);                          \
        }                                                                       \
        asm volatile("cp.async.commit_group;");                                 \
    } while (0)

    STAGE1(0, 0);
    STAGE1(1, 1);
    asm volatile("cp.async.wait_group 1;");
    __syncthreads();
    MMA_TILE(smA0);                               // iter 0 (buf 0)
    asm volatile("cp.async.wait_group 0;");
    __syncthreads();
    MMA_TILE(smA0 + STGH * 2);                    // iter 1 (buf 1)
    pdl_wait();
    __syncthreads();
    STAGE1(2, 0);
    STAGE1(3, 1);
#pragma unroll 1
    for (int t = 2; t < 8; t++) {
        if (t < 7) asm volatile("cp.async.wait_group 1;");
        else       asm volatile("cp.async.wait_group 0;");
        __syncthreads();
        const uint32_t aB = smA0 + (t & 1) * (STGH * 2);
        MMA_TILE(aB);
        __syncthreads();
        if (t < 6) STAGE1(t + 2, t & 1);
    }
    pdl_trigger();

    // ---- epilogue ----
    if (nc0 < 384) {
        const float* hsrc[3];
        hsrc[0] = (j > 0)          ? g_H + ((size_t)(p - 1 ) * BSZ + b0) * 128 : nullptr;
        hsrc[1] = (i > 0)          ? g_H + ((size_t)(p - 32) * BSZ + b0) * 128 : nullptr;
        hsrc[2] = (i > 0 && j > 0) ? g_H + ((size_t)(p - 33) * BSZ + b0) * 128 : nullptr;
#pragma unroll
        for (int mt = 0; mt < 2; mt++) {
#pragma unroll
            for (int half = 0; half < 2; half++) {
                int lr = wm * 32 + mt * 16 + ql + half * 8;
                int Mr = Mbase + lr;
#pragma unroll
                for (int nt = 0; nt < 4; nt++) {
                    int c = nc0 + wn * 32 + nt * 8 + 2 * qj;
                    float v0 = acc[mt][nt][half * 2 + 0] + g_bP[c];
                    float v1 = acc[mt][nt][half * 2 + 1] + g_bP[c + 1];
                    v0 = fminf(fmaxf(0.2f * v0 + 0.5f, 0.f), 1.f);
                    v1 = fminf(fmaxf(0.2f * v1 + 0.5f, 0.f), 1.f);
                    int seg = c >> 7, u = c & 127;
                    const float* hp = hsrc[seg];
                    float h0 = hp ? hp[lr * 128 + u]     : 0.f;
                    float h1 = hp ? hp[lr * 128 + u + 1] : 0.f;
                    *(__half2*)&g_A2[(size_t)Mr * 384 + c] =
                        __floats2half2_rn(v0 * h0, v1 * h1);
                }
            }
        }
    } else {
#pragma unroll
        for (int mt = 0; mt < 2; mt++) {
#pragma unroll
            for (int half = 0; half < 2; half++) {
                int lr = wm * 32 + mt * 16 + ql + half * 8;
                int Mr = Mbase + lr;
#pragma unroll
                for (int nt = 0; nt < 4; nt++) {
                    int c = nc0 + wn * 32 + nt * 8 + 2 * qj;
                    float z0 = acc[mt][nt][half * 2 + 0] + g_bP[c];
                    float z1 = acc[mt][nt][half * 2 + 1] + g_bP[c + 1];
                    float q0 = __shfl_xor_sync(0xffffffffu, z0, 1);
                    float q1 = __shfl_xor_sync(0xffffffffu, z1, 1);
                    float mx = fmaxf(fmaxf(z0, z1), fmaxf(q0, q1));
                    float e0 = __expf(z0 - mx), e1 = __expf(z1 - mx);
                    float s2 = e0 + e1;
                    float st = s2 + __shfl_xor_sync(0xffffffffu, s2, 1);
                    float inv = 1.f / st;
                    int cc = c - 384, u = cc >> 2, g = cc & 3;
                    *(float2*)&g_Z[(size_t)Mr * 512 + u * 4 + g] =
                        make_float2(e0 * inv, e1 * inv);
                }
            }
        }
    }
}

// ---------------------------------------------------------------------------
// K2: 64x128x512 tiles, grid = nc*4, 512 thr, 4x4 warp grid of 16x32 tiles.
#define AHALF2 (64 * STRH)
#define STGH2  (AHALF2 + 128 * STRH)
#define SMEM2  (2 * STGH2 * 2)          // 55296

#define MMA_TILE2(aB_)  do {                                                     \
        const uint32_t bBv_ = (aB_) + AHALF2 * 2;                                \
        _Pragma("unroll")                                                        \
        for (int k16 = 0; k16 < 4; k16++) {                                      \
            const uint32_t kb2 = k16 * 32;                                       \
            uint32_t af[4];                                                      \
            ldsm4(af, (aB_) + aOff0 + kb2);                                      \
            _Pragma("unroll")                                                    \
            for (int nt = 0; nt < 4; nt++) {                                     \
                uint32_t bf[2];                                                  \
                ldsm2(bf, bBv_ + bOff + nt * (8 * STRH * 2) + kb2);              \
                mma16(acc[nt], af, bf[0], bf[1]);                                \
            }                                                                    \
        }                                                                        \
    } while (0)

__global__ __launch_bounds__(NTHR) void k2_kernel(int d, const float* __restrict__ bias,
                                                  float* __restrict__ out) {
    extern __shared__ __half sm[];
    const uint32_t smA0 = (uint32_t)__cvta_generic_to_shared(sm);

    const int tid = threadIdx.x, lane = tid & 31, warp = tid >> 5;
    const int wm = warp >> 2, wn = warp & 3, qj = lane & 3, ql = lane >> 2;
    const int i0 = (d > 31) ? d - 31 : 0;
    const int Mbase = blockIdx.x * 64;
    const int cell = Mbase >> 8, b0 = Mbase & 255;
    const int i = i0 + cell, j = d - i, p = i * 32 + j;

    const int l15 = lane & 15, lhi = lane >> 4;
    const uint32_t aOff0 = ((wm * 16 + l15) * STRH + lhi * 8) * 2;
    const uint32_t bOff  = ((wn * 32 + (lane & 7)) * STRH + ((lane >> 3) & 1) * 8) * 2;

    const __half* Tsrc = g_Th + ((size_t)p * BSZ + b0) * 128;
    float acc[4][4] = {};

    // stage t: t<2 -> Tsrc k_off t*64, U2T rows 384+t*64 ; t>=2 -> A2 (t-2)*64
#define STAGE2(t, buf) do {                                                     \
        uint32_t aB_ = smA0 + (buf) * (STGH2 * 2);                              \
        uint32_t bB_ = aB_ + AHALF2 * 2;                                        \
        {                                                                       \
            int m_ = tid >> 3, c_ = tid & 7;                                    \
            const __half* sp_;                                                  \
            if ((t) < 2) sp_ = Tsrc + (size_t)m_ * 128 + (t) * 64 + c_ * 8;             \
            else         sp_ = g_A2 + (size_t)(Mbase + m_) * 384 + ((t) - 2) * 64 + c_ * 8; \
            cp16(aB_ + (m_ * STRH + c_ * 8) * 2, sp_, 16);                      \
        }                                                                       \
        const __half* up_ = g_U2T + (((t) < 2) ? (384 + (t) * 64) : (((t) - 2) * 64)); \
        _Pragma("unroll")                                                       \
        for (int r_ = 0; r_ < 2; r_++) {                                        \
            int ix_ = tid + r_ * NTHR;                                          \
            int n_ = ix_ >> 3, c_ = ix_ & 7;                                    \
            cp16(bB_ + (n_ * STRH + c_ * 8) * 2,                                \
                 up_ + (size_t)n_ * 512 + c_ * 8, 16);                          \
        }                                                                       \
        asm volatile("cp.async.commit_group;");                                 \
    } while (0)

    STAGE2(0, 0);
    STAGE2(1, 1);
    asm volatile("cp.async.wait_group 1;");
    __syncthreads();
    MMA_TILE2(smA0);                              // iter 0 (buf 0)
    asm volatile("cp.async.wait_group 0;");
    __syncthreads();
    MMA_TILE2(smA0 + STGH2 * 2);                  // iter 1 (buf 1)
    pdl_wait();
    __syncthreads();
    STAGE2(2, 0);
    STAGE2(3, 1);
#pragma unroll 1
    for (int t = 2; t < 8; t++) {
        if (t < 7) asm volatile("cp.async.wait_group 1;");
        else       asm volatile("cp.async.wait_group 0;");
        __syncthreads();
        const uint32_t aB = smA0 + (t & 1) * (STGH2 * 2);
        MMA_TILE2(aB);
        __syncthreads();
        if (t < 6) STAGE2(t + 2, t & 1);
    }
    pdl_trigger();

    const float* hL = (j > 0)          ? g_H + ((size_t)(p - 1 ) * BSZ + b0) * 128 : nullptr;
    const float* hT = (i > 0)          ? g_H + ((size_t)(p - 32) * BSZ + b0) * 128 : nullptr;
    const float* hD = (i > 0 && j > 0) ? g_H + ((size_t)(p - 33) * BSZ + b0) * 128 : nullptr;
    float*  Hd  = g_H  + ((size_t)p * BSZ + b0) * 128;
    __half* Hrd = g_Hr + ((size_t)p * BSZ + b0) * 128;

#pragma unroll
    for (int half = 0; half < 2; half++) {
        int lr = wm * 16 + ql + half * 8;
        int Mr = Mbase + lr;
#pragma unroll
        for (int nt = 0; nt < 4; nt++) {
            int u = wn * 32 + nt * 8 + 2 * qj;
            float a0 = acc[nt][half * 2 + 0] + bias[896 + u];
            float a1 = acc[nt][half * 2 + 1] + bias[896 + u + 1];
            float hs0 = tanhf(a0), hs1 = tanhf(a1);
            float4 z0 = *(const float4*)&g_Z[(size_t)Mr * 512 + u * 4];
            float4 z1 = *(const float4*)&g_Z[(size_t)Mr * 512 + (u + 1) * 4];
            float l0 = hL ? hL[lr * 128 + u] : 0.f, l1 = hL ? hL[lr * 128 + u + 1] : 0.f;
            float t0 = hT ? hT[lr * 128 + u] : 0.f, t1 = hT ? hT[lr * 128 + u + 1] : 0.f;
            float d0 = hD ? hD[lr * 128 + u] : 0.f, d1 = hD ? hD[lr * 128 + u + 1] : 0.f;
            float h0 = z0.y * l0 + z0.z * t0 + z0.w * d0 + z0.x * hs0;
            float h1 = z1.y * l1 + z1.z * t1 + z1.w * d1 + z1.x * hs1;
            *(float2*)&Hd[lr * 128 + u]   = make_float2(h0, h1);
            *(__half2*)&Hrd[lr * 128 + u] = __floats2half2_rn(h0, h1);
            if (p == 1023)
                *(float2*)&out[(size_t)(b0 + lr) * 128 + u] = make_float2(h0, h1);
        }
    }
}

// ---------------------------------------------------------------------------
extern "C" void kernel_launch(void* const* d_in, const int* in_sizes, int n_in,
                              void* d_out, int out_size) {
    const float* inputs = (const float*)d_in[0];
    const float* W      = (const float*)d_in[1];
    const float* Umat   = (const float*)d_in[2];
    const float* bias   = (const float*)d_in[3];
    const float* w_ij   = (const float*)d_in[4];
    float* out = (float*)d_out;

    cudaFuncSetAttribute(k1_kernel, cudaFuncAttributeMaxDynamicSharedMemorySize, SMEM1);
    cudaFuncSetAttribute(k2_kernel, cudaFuncAttributeMaxDynamicSharedMemorySize, SMEM2);

    transpose_kernel<<<dim3(32, 1024), dim3(32, 8)>>>(inputs);
    prep_all_kernel<<<(NWT + NUT + 896 + 255) / 256, 256>>>(W, Umat, w_ij, bias);

    cudaLaunchAttribute attrs[1];
    attrs[0].id = cudaLaunchAttributeProgrammaticStreamSerialization;
    attrs[0].val.programmaticStreamSerializationAllowed = 1;

    for (int d = 0; d <= 62; d++) {
        int i0 = (d > 31) ? d - 31 : 0;
        int i1 = (d < 31) ? d : 31;
        int nc = i1 - i0 + 1;

        if (d == 0) {
            k1_kernel<<<dim3(7, nc * 2), NTHR, SMEM1>>>(d);
        } else {
            cudaLaunchConfig_t c1 = {};
            c1.gridDim = dim3(7, nc * 2); c1.blockDim = dim3(NTHR);
            c1.dynamicSmemBytes = SMEM1; c1.stream = 0;
            c1.attrs = attrs; c1.numAttrs = 1;
            cudaLaunchKernelEx(&c1, k1_kernel, d);
        }
        cudaLaunchConfig_t c2 = {};
        c2.gridDim = dim3(nc * 4); c2.blockDim = dim3(NTHR);
        c2.dynamicSmemBytes = SMEM2; c2.stream = 0;
        c2.attrs = attrs; c2.numAttrs = 1;
        cudaLaunchKernelEx(&c2, k2_kernel, d, bias, out);
    }
    (void)in_sizes; (void)n_in; (void)out_size;
}